// round 10
// baseline (speedup 1.0000x reference)
#include <cuda_runtime.h>
#include <cuda_bf16.h>
#include <cstdint>

#define WSZ 7
#define SHIFT 3
#define HEADS 16
#define NTOK 49
#define CDIM 512
#define DHEAD 32
#define HH 56
#define NWIN 1024
#define MROWS (NWIN*NTOK)   // 50176
#define NPIX  MROWS

typedef unsigned long long ull;

__device__ unsigned g_xbf[(size_t)NPIX*256];              // x bf16 [pix][512]
__device__ unsigned g_wqkv_t[1536*256];                   // qkv_w^T bf16 [n][k]
__device__ unsigned g_wproj_t[512*256];                   // proj_w^T bf16 [n][k]
__device__ unsigned g_qkvb[(size_t)3*NWIN*HEADS*NTOK*16]; // qkv bf16 [s][win][head][tok][32]
__device__ unsigned g_attnb[(size_t)MROWS*256];           // attn out bf16 [row][512]

__device__ __forceinline__ int row_to_pixel(int r) {
    int win = r / NTOK, t = r - win * NTOK;
    int b  = win >> 6;
    int wy = (win >> 3) & 7;
    int wx = win & 7;
    int ty = t / WSZ, tx = t - ty * WSZ;
    int hs = wy * WSZ + ty;
    int ws = wx * WSZ + tx;
    int h = hs + SHIFT; if (h >= HH) h -= HH;
    int w = ws + SHIFT; if (w >= HH) w -= HH;
    return (b * HH + h) * HH + w;
}

__device__ __forceinline__ unsigned pkbf(float lo, float hi) {
    unsigned r; asm("cvt.rn.bf16x2.f32 %0, %1, %2;" : "=r"(r) : "f"(hi), "f"(lo)); return r;
}
__device__ __forceinline__ ull pack2(float x) {
    ull r; asm("mov.b64 %0, {%1, %1};" : "=l"(r) : "f"(x)); return r;
}
__device__ __forceinline__ void fma2(ull& d, ull a, ull b) {
    asm("fma.rn.f32x2 %0, %1, %2, %3;" : "=l"(d) : "l"(a), "l"(b), "l"(d));
}
__device__ __forceinline__ float2 unpack2(ull v) {
    float2 f; asm("mov.b64 {%0, %1}, %2;" : "=f"(f.x), "=f"(f.y) : "l"(v)); return f;
}
__device__ __forceinline__ void expand8(float* dst, uint4 v) {
    unsigned a[4] = {v.x, v.y, v.z, v.w};
#pragma unroll
    for (int i = 0; i < 4; i++) {
        dst[2*i]   = __uint_as_float(a[i] << 16);
        dst[2*i+1] = __uint_as_float(a[i] & 0xffff0000u);
    }
}
__device__ __forceinline__ unsigned s2u(const void* p) {
    return (unsigned)__cvta_generic_to_shared(p);
}
__device__ __forceinline__ void ldsm4(unsigned* r, unsigned a) {
    asm volatile("ldmatrix.sync.aligned.m8n8.x4.shared.b16 {%0,%1,%2,%3}, [%4];"
                 : "=r"(r[0]), "=r"(r[1]), "=r"(r[2]), "=r"(r[3]) : "r"(a));
}
__device__ __forceinline__ void mma_bf16(float* d, const unsigned* a, const unsigned* b) {
    asm volatile(
        "mma.sync.aligned.m16n8k16.row.col.f32.bf16.bf16.f32 "
        "{%0,%1,%2,%3}, {%4,%5,%6,%7}, {%8,%9}, {%0,%1,%2,%3};"
        : "+f"(d[0]), "+f"(d[1]), "+f"(d[2]), "+f"(d[3])
        : "r"(a[0]), "r"(a[1]), "r"(a[2]), "r"(a[3]), "r"(b[0]), "r"(b[1]));
}
__device__ __forceinline__ void cp16(unsigned dst, const void* src) {
    asm volatile("cp.async.cg.shared.global [%0], [%1], 16;" :: "r"(dst), "l"(src) : "memory");
}
__device__ __forceinline__ void cp_commit() { asm volatile("cp.async.commit_group;" ::: "memory"); }
__device__ __forceinline__ void cp_wait1()  { asm volatile("cp.async.wait_group 1;" ::: "memory"); }
__device__ __forceinline__ void cp_wait0()  { asm volatile("cp.async.wait_group 0;" ::: "memory"); }

#define STR 40   // smem row stride (bf16) = 80B -> conflict-free LDSM
#define NSTAGE 3

// ---------------------------------------------------------------------------
// Prepasses
// ---------------------------------------------------------------------------
__global__ void cvt_x_kernel(const float* __restrict__ x) {
    size_t i = (size_t)blockIdx.x * 256 + threadIdx.x;
    float4 v = *reinterpret_cast<const float4*>(x + i * 4);
    uint2 o = { pkbf(v.x, v.y), pkbf(v.z, v.w) };
    *reinterpret_cast<uint2*>(&g_xbf[i * 2]) = o;
}
__global__ void wtrans_kernel(const float* __restrict__ w, int ncols, int which) {
    int n = blockIdx.x, t = threadIdx.x;
    float a = w[(size_t)(2 * t)     * ncols + n];
    float b = w[(size_t)(2 * t + 1) * ncols + n];
    unsigned v = pkbf(a, b);
    if (which) g_wproj_t[n * 256 + t] = v; else g_wqkv_t[n * 256 + t] = v;
}

// ---------------------------------------------------------------------------
// Kernel 1: QKV GEMM. CTA tile 128(M)x64(N), warp tile 32x32, 3-stage cp.async.
// ---------------------------------------------------------------------------
__global__ __launch_bounds__(256, 2) void qkv_gemm(const float* __restrict__ bias) {
    __shared__ __align__(16) unsigned short As[NSTAGE][128][STR];
    __shared__ __align__(16) unsigned short Bs[NSTAGE][64][STR];
    __shared__ int rowoff[128];

    const int tid = threadIdx.x;
    const int row0 = blockIdx.y * 128, col0 = blockIdx.x * 64;
    const int lane = tid & 31, wid = tid >> 5;
    const int wm = wid >> 1, wn = wid & 1;

    if (tid < 128) rowoff[tid] = row_to_pixel(row0 + tid) * 256;
    __syncthreads();

    float acc[8][4];
#pragma unroll
    for (int i = 0; i < 8; i++)
#pragma unroll
        for (int j = 0; j < 4; j++) acc[i][j] = 0.0f;

    // staging: A 128 rows x 4 segs = 512 cp16 (2/thread), B 64 x 4 = 256 (1/thread)
    const int a_sr = tid >> 1, a_ss = (tid & 1) * 2;     // A row, first of 2 segs
    const int b_sr = tid >> 2, b_ss = tid & 3;           // B row, seg

    auto stage = [&](int buf, int kt) {
        const int k16 = kt * 16;
#pragma unroll
        for (int q = 0; q < 2; q++)
            cp16(s2u(&As[buf][a_sr][(a_ss + q) * 8]),
                 &g_xbf[(size_t)rowoff[a_sr] + k16 + (a_ss + q) * 4]);
        cp16(s2u(&Bs[buf][b_sr][b_ss * 8]),
             &g_wqkv_t[(size_t)(col0 + b_sr) * 256 + k16 + b_ss * 4]);
    };

    stage(0, 0); cp_commit();
    stage(1, 1); cp_commit();

    const unsigned a_base = s2u(&As[0][0][0]);
    const unsigned b_base = s2u(&Bs[0][0][0]);
    const unsigned a_sz = 128 * STR * 2, b_sz = 64 * STR * 2;
    const int a_row = wm * 32 + (lane & 15);
    const int a_colB = (lane >> 4) * 16;
    const int b_row = wn * 32 + ((lane >> 4) & 1) * 8 + (lane & 7);
    const int b_colB = ((lane >> 3) & 1) * 16;

    int buf = 0, sbuf = 2;
#pragma unroll 1
    for (int t = 0; t < 16; t++) {
        if (t < 15) cp_wait1(); else cp_wait0();
        __syncthreads();
        if (t < 14) { stage(sbuf, t + 2); cp_commit(); }
        const unsigned ab = a_base + buf * a_sz;
        const unsigned bb = b_base + buf * b_sz;
#pragma unroll
        for (int ks = 0; ks < 2; ks++) {
            unsigned afr[2][4], bfr[2][4];
#pragma unroll
            for (int mt = 0; mt < 2; mt++)
                ldsm4(afr[mt], ab + (unsigned)((a_row + mt * 16) * (STR * 2) + ks * 32 + a_colB));
#pragma unroll
            for (int n2 = 0; n2 < 2; n2++)
                ldsm4(bfr[n2], bb + (unsigned)((b_row + n2 * 16) * (STR * 2) + ks * 32 + b_colB));
#pragma unroll
            for (int mt = 0; mt < 2; mt++)
#pragma unroll
                for (int nt = 0; nt < 4; nt++)
                    mma_bf16(acc[mt * 4 + nt], afr[mt], &bfr[nt >> 1][(nt & 1) * 2]);
        }
        buf = (buf == NSTAGE - 1) ? 0 : buf + 1;
        sbuf = (sbuf == NSTAGE - 1) ? 0 : sbuf + 1;
    }

    // epilogue: +bias, pack bf16, scatter into g_qkvb
#pragma unroll
    for (int mt = 0; mt < 2; mt++) {
#pragma unroll
        for (int half = 0; half < 2; half++) {
            int r = row0 + wm * 32 + mt * 16 + (lane >> 2) + half * 8;
            int win = r / NTOK, tok = r - win * NTOK;
#pragma unroll
            for (int nt = 0; nt < 4; nt++) {
                int c = col0 + wn * 32 + nt * 8 + (lane & 3) * 2;
                int s = c >> 9, head = (c >> 5) & 15, dd = c & 31;
                size_t ub = (((size_t)s * NWIN + win) * HEADS + head) * (NTOK * 16)
                          + (size_t)tok * 16 + (dd >> 1);
                float lo = acc[mt * 4 + nt][half * 2]     + bias[c];
                float hi = acc[mt * 4 + nt][half * 2 + 1] + bias[c + 1];
                g_qkvb[ub] = pkbf(lo, hi);
            }
        }
    }
}

// ---------------------------------------------------------------------------
// Kernel 2: windowed attention, bf16 IO, f32x2 math, warp-per-row softmax.
// ---------------------------------------------------------------------------
__global__ __launch_bounds__(256) void attn_kernel(const float* __restrict__ table) {
    const int wh = blockIdx.x;
    const int win = wh >> 4;
    const int head = wh & 15;
    const int tid = threadIdx.x;
    const int lane = tid & 31, wid = tid >> 5;

    __shared__ float qs[NTOK * 36];
    __shared__ float ks_[NTOK * 36];
    __shared__ float vs[NTOK * 36];
    __shared__ float S[NTOK * NTOK];
    __shared__ float tbl[169];
    __shared__ int reg[NTOK];

    const size_t SOFF2 = (size_t)NWIN * HEADS * NTOK * 16;
    const size_t base2 = ((size_t)win * HEADS + head) * (NTOK * 16);

    if (tid < 196) {
        int t = tid >> 2, ub = (tid & 3) * 4, dd = (tid & 3) * 8;
        uint4 q4 = *reinterpret_cast<const uint4*>(&g_qkvb[base2 + t * 16 + ub]);
        uint4 k4 = *reinterpret_cast<const uint4*>(&g_qkvb[SOFF2 + base2 + t * 16 + ub]);
        uint4 v4 = *reinterpret_cast<const uint4*>(&g_qkvb[2 * SOFF2 + base2 + t * 16 + ub]);
        expand8(&qs[t * 36 + dd], q4);
        expand8(&ks_[t * 36 + dd], k4);
        expand8(&vs[t * 36 + dd], v4);
    }
    if (tid < 169) tbl[tid] = table[tid * HEADS + head];
    if (tid >= 200 && tid < 200 + NTOK) {
        int t = tid - 200;
        int wy = (win >> 3) & 7, wx = win & 7;
        int ty = t / WSZ, tx = t - ty * WSZ;
        int hs = wy * WSZ + ty, ws = wx * WSZ + tx;
        int rh = (hs < 49) ? 0 : ((hs < 53) ? 1 : 2);
        int rw = (ws < 49) ? 0 : ((ws < 53) ? 1 : 2);
        reg[t] = rh * 3 + rw;
    }
    __syncthreads();

    const float scale = 0.17677669529663687f;

    if (tid < 196) {
        const int i = tid >> 2, jq = tid & 3;
        const int j0 = jq * 13, j1 = (jq == 3) ? 49 : j0 + 13;
        ull qv[16];
#pragma unroll
        for (int p = 0; p < 16; p++)
            qv[p] = *reinterpret_cast<const ull*>(&qs[i * 36 + 2 * p]);
        const int iy = i / WSZ, ix = i - iy * WSZ;
        const int ri = reg[i];
        for (int j = j0; j < j1; j++) {
            ull a0 = 0ull, a1 = 0ull;
            const ull* kp = reinterpret_cast<const ull*>(&ks_[j * 36]);
#pragma unroll
            for (int p = 0; p < 16; p += 2) { fma2(a0, qv[p], kp[p]); fma2(a1, qv[p+1], kp[p+1]); }
            float2 f0 = unpack2(a0), f1 = unpack2(a1);
            float d = (f0.x + f0.y) + (f1.x + f1.y);
            int jy = j / WSZ, jx = j - jy * WSZ;
            int ridx = (iy - jy + 6) * 13 + (ix - jx + 6);
            float m = (ri != reg[j]) ? -100.0f : 0.0f;
            S[i * NTOK + j] = d * scale + tbl[ridx] + m;
        }
    }
    __syncthreads();

    // warp-per-row softmax: 8 warps cover 49 rows
    for (int i = wid; i < NTOK; i += 8) {
        float v0 = S[i * NTOK + lane];                       // lane < 49 always
        float v1 = (lane + 32 < NTOK) ? S[i * NTOK + lane + 32] : -1e30f;
        float mx = fmaxf(v0, v1);
#pragma unroll
        for (int off = 16; off; off >>= 1)
            mx = fmaxf(mx, __shfl_xor_sync(0xffffffffu, mx, off));
        float e0 = (lane < NTOK) ? __expf(v0 - mx) : 0.0f;
        float e1 = (lane + 32 < NTOK) ? __expf(v1 - mx) : 0.0f;
        float sum = e0 + e1;
#pragma unroll
        for (int off = 16; off; off >>= 1)
            sum += __shfl_xor_sync(0xffffffffu, sum, off);
        float inv = 1.0f / sum;
        S[i * NTOK + lane] = e0 * inv;
        if (lane + 32 < NTOK) S[i * NTOK + lane + 32] = e1 * inv;
    }
    __syncthreads();

    for (int idx = tid; idx < 392; idx += 256) {
        int i = idx >> 3, dq = (idx & 7) * 4;
        ull o0 = 0ull, o1 = 0ull;
        const float* sp = &S[i * NTOK];
        for (int j = 0; j < NTOK; j++) {
            ull sv = pack2(sp[j]);
            const ull* vp = reinterpret_cast<const ull*>(&vs[j * 36 + dq]);
            fma2(o0, sv, vp[0]);
            fma2(o1, sv, vp[1]);
        }
        float2 a = unpack2(o0), b = unpack2(o1);
        uint2 ov = { pkbf(a.x, a.y), pkbf(b.x, b.y) };
        *reinterpret_cast<uint2*>(&g_attnb[((size_t)win * NTOK + i) * 256 + head * 16 + (dq >> 1)]) = ov;
    }
}

// ---------------------------------------------------------------------------
// Kernel 3: proj GEMM + window reverse + bias + residual (f32 out)
// ---------------------------------------------------------------------------
__global__ __launch_bounds__(256, 2) void proj_gemm(const float* __restrict__ x,
                                                    const float* __restrict__ bias,
                                                    float* __restrict__ out) {
    __shared__ __align__(16) unsigned short As[NSTAGE][128][STR];
    __shared__ __align__(16) unsigned short Bs[NSTAGE][64][STR];

    const int tid = threadIdx.x;
    const int row0 = blockIdx.y * 128, col0 = blockIdx.x * 64;
    const int lane = tid & 31, wid = tid >> 5;
    const int wm = wid >> 1, wn = wid & 1;

    float acc[8][4];
#pragma unroll
    for (int i = 0; i < 8; i++)
#pragma unroll
        for (int j = 0; j < 4; j++) acc[i][j] = 0.0f;

    const int a_sr = tid >> 1, a_ss = (tid & 1) * 2;
    const int b_sr = tid >> 2, b_ss = tid & 3;

    auto stage = [&](int buf, int kt) {
        const int k16 = kt * 16;
#pragma unroll
        for (int q = 0; q < 2; q++)
            cp16(s2u(&As[buf][a_sr][(a_ss + q) * 8]),
                 &g_attnb[(size_t)(row0 + a_sr) * 256 + k16 + (a_ss + q) * 4]);
        cp16(s2u(&Bs[buf][b_sr][b_ss * 8]),
             &g_wproj_t[(size_t)(col0 + b_sr) * 256 + k16 + b_ss * 4]);
    };

    stage(0, 0); cp_commit();
    stage(1, 1); cp_commit();

    const unsigned a_base = s2u(&As[0][0][0]);
    const unsigned b_base = s2u(&Bs[0][0][0]);
    const unsigned a_sz = 128 * STR * 2, b_sz = 64 * STR * 2;
    const int a_row = wm * 32 + (lane & 15);
    const int a_colB = (lane >> 4) * 16;
    const int b_row = wn * 32 + ((lane >> 4) & 1) * 8 + (lane & 7);
    const int b_colB = ((lane >> 3) & 1) * 16;

    int buf = 0, sbuf = 2;
#pragma unroll 1
    for (int t = 0; t < 16; t++) {
        if (t < 15) cp_wait1(); else cp_wait0();
        __syncthreads();
        if (t < 14) { stage(sbuf, t + 2); cp_commit(); }
        const unsigned ab = a_base + buf * a_sz;
        const unsigned bb = b_base + buf * b_sz;
#pragma unroll
        for (int ks = 0; ks < 2; ks++) {
            unsigned afr[2][4], bfr[2][4];
#pragma unroll
            for (int mt = 0; mt < 2; mt++)
                ldsm4(afr[mt], ab + (unsigned)((a_row + mt * 16) * (STR * 2) + ks * 32 + a_colB));
#pragma unroll
            for (int n2 = 0; n2 < 2; n2++)
                ldsm4(bfr[n2], bb + (unsigned)((b_row + n2 * 16) * (STR * 2) + ks * 32 + b_colB));
#pragma unroll
            for (int mt = 0; mt < 2; mt++)
#pragma unroll
                for (int nt = 0; nt < 4; nt++)
                    mma_bf16(acc[mt * 4 + nt], afr[mt], &bfr[nt >> 1][(nt & 1) * 2]);
        }
        buf = (buf == NSTAGE - 1) ? 0 : buf + 1;
        sbuf = (sbuf == NSTAGE - 1) ? 0 : sbuf + 1;
    }

#pragma unroll
    for (int mt = 0; mt < 2; mt++) {
#pragma unroll
        for (int half = 0; half < 2; half++) {
            int r = row0 + wm * 32 + mt * 16 + (lane >> 2) + half * 8;
            size_t pix = (size_t)row_to_pixel(r) * CDIM;
#pragma unroll
            for (int nt = 0; nt < 4; nt++) {
                int c = col0 + wn * 32 + nt * 8 + (lane & 3) * 2;
                float2 bv2 = *reinterpret_cast<const float2*>(bias + c);
                float2 xv  = *reinterpret_cast<const float2*>(x + pix + c);
                float2 ov;
                ov.x = xv.x + acc[mt * 4 + nt][half * 2]     + bv2.x;
                ov.y = xv.y + acc[mt * 4 + nt][half * 2 + 1] + bv2.y;
                *reinterpret_cast<float2*>(&out[pix + c]) = ov;
            }
        }
    }
}

extern "C" void kernel_launch(void* const* d_in, const int* in_sizes, int n_in,
                              void* d_out, int out_size) {
    const float* x      = (const float*)d_in[0];
    const float* qkv_w  = (const float*)d_in[1];
    const float* qkv_b  = (const float*)d_in[2];
    const float* proj_w = (const float*)d_in[3];
    const float* proj_b = (const float*)d_in[4];
    const float* table  = (const float*)d_in[5];
    float* out = (float*)d_out;

    cvt_x_kernel<<<(NPIX * 512 / 4) / 256, 256>>>(x);
    wtrans_kernel<<<1536, 256>>>(qkv_w, 1536, 0);
    wtrans_kernel<<<512, 256>>>(proj_w, 512, 1);

    qkv_gemm<<<dim3(24, 392), 256>>>(qkv_b);
    attn_kernel<<<NWIN * HEADS, 256>>>(table);
    proj_gemm<<<dim3(8, 392), 256>>>(x, proj_b, out);
}

// round 11
// speedup vs baseline: 1.4813x; 1.4813x over previous
#include <cuda_runtime.h>
#include <cuda_bf16.h>
#include <cstdint>

#define WSZ 7
#define SHIFT 3
#define HEADS 16
#define NTOK 49
#define CDIM 512
#define DHEAD 32
#define HH 56
#define NWIN 1024
#define MROWS (NWIN*NTOK)   // 50176
#define NPIX  MROWS

typedef unsigned long long ull;

__device__ unsigned g_xbf[(size_t)NPIX*256];              // x bf16 [pix][512]
__device__ unsigned g_wqkv_t[1536*256];                   // qkv_w^T bf16 [n][k]
__device__ unsigned g_wproj_t[512*256];                   // proj_w^T bf16 [n][k]
__device__ unsigned g_qkvb[(size_t)3*NWIN*HEADS*NTOK*16]; // qkv bf16 [s][win][head][tok][32]
__device__ unsigned g_attnb[(size_t)MROWS*256];           // attn out bf16 [row][512]

__device__ __forceinline__ int row_to_pixel(int r) {
    int win = r / NTOK, t = r - win * NTOK;
    int b  = win >> 6;
    int wy = (win >> 3) & 7;
    int wx = win & 7;
    int ty = t / WSZ, tx = t - ty * WSZ;
    int hs = wy * WSZ + ty;
    int ws = wx * WSZ + tx;
    int h = hs + SHIFT; if (h >= HH) h -= HH;
    int w = ws + SHIFT; if (w >= HH) w -= HH;
    return (b * HH + h) * HH + w;
}

__device__ __forceinline__ unsigned pkbf(float lo, float hi) {
    unsigned r; asm("cvt.rn.bf16x2.f32 %0, %1, %2;" : "=r"(r) : "f"(hi), "f"(lo)); return r;
}
__device__ __forceinline__ ull pack2(float x) {
    ull r; asm("mov.b64 %0, {%1, %1};" : "=l"(r) : "f"(x)); return r;
}
__device__ __forceinline__ void fma2(ull& d, ull a, ull b) {
    asm("fma.rn.f32x2 %0, %1, %2, %3;" : "=l"(d) : "l"(a), "l"(b), "l"(d));
}
__device__ __forceinline__ float2 unpack2(ull v) {
    float2 f; asm("mov.b64 {%0, %1}, %2;" : "=f"(f.x), "=f"(f.y) : "l"(v)); return f;
}
__device__ __forceinline__ void expand8(float* dst, uint4 v) {
    unsigned a[4] = {v.x, v.y, v.z, v.w};
#pragma unroll
    for (int i = 0; i < 4; i++) {
        dst[2*i]   = __uint_as_float(a[i] << 16);
        dst[2*i+1] = __uint_as_float(a[i] & 0xffff0000u);
    }
}
__device__ __forceinline__ unsigned s2u(const void* p) {
    return (unsigned)__cvta_generic_to_shared(p);
}
__device__ __forceinline__ void ldsm4(unsigned* r, unsigned a) {
    asm volatile("ldmatrix.sync.aligned.m8n8.x4.shared.b16 {%0,%1,%2,%3}, [%4];"
                 : "=r"(r[0]), "=r"(r[1]), "=r"(r[2]), "=r"(r[3]) : "r"(a));
}
__device__ __forceinline__ void mma_bf16(float* d, const unsigned* a, const unsigned* b) {
    asm volatile(
        "mma.sync.aligned.m16n8k16.row.col.f32.bf16.bf16.f32 "
        "{%0,%1,%2,%3}, {%4,%5,%6,%7}, {%8,%9}, {%0,%1,%2,%3};"
        : "+f"(d[0]), "+f"(d[1]), "+f"(d[2]), "+f"(d[3])
        : "r"(a[0]), "r"(a[1]), "r"(a[2]), "r"(a[3]), "r"(b[0]), "r"(b[1]));
}
__device__ __forceinline__ void cp16(unsigned dst, const void* src) {
    asm volatile("cp.async.cg.shared.global [%0], [%1], 16;" :: "r"(dst), "l"(src) : "memory");
}
__device__ __forceinline__ void cp_commit() { asm volatile("cp.async.commit_group;" ::: "memory"); }
__device__ __forceinline__ void cp_wait1()  { asm volatile("cp.async.wait_group 1;" ::: "memory"); }
__device__ __forceinline__ void cp_wait0()  { asm volatile("cp.async.wait_group 0;" ::: "memory"); }

#define STR 40   // smem row stride (bf16) = 80B -> conflict-free LDSM
#define NSTAGE 3

// ---------------------------------------------------------------------------
// Prepasses
// ---------------------------------------------------------------------------
__global__ void cvt_x_kernel(const float* __restrict__ x) {
    size_t i = (size_t)blockIdx.x * 256 + threadIdx.x;
    float4 v = *reinterpret_cast<const float4*>(x + i * 4);
    uint2 o = { pkbf(v.x, v.y), pkbf(v.z, v.w) };
    *reinterpret_cast<uint2*>(&g_xbf[i * 2]) = o;
}
__global__ void wtrans_kernel(const float* __restrict__ w, int ncols, int which) {
    int n = blockIdx.x, t = threadIdx.x;
    float a = w[(size_t)(2 * t)     * ncols + n];
    float b = w[(size_t)(2 * t + 1) * ncols + n];
    unsigned v = pkbf(a, b);
    if (which) g_wproj_t[n * 256 + t] = v; else g_wqkv_t[n * 256 + t] = v;
}

// ---------------------------------------------------------------------------
// Kernel 1: QKV GEMM. CTA 128x128, warp tile 64x32, 3-stage cp.async pipeline.
// ---------------------------------------------------------------------------
__global__ __launch_bounds__(256, 1) void qkv_gemm(const float* __restrict__ bias) {
    __shared__ __align__(16) unsigned short As[NSTAGE][128][STR];
    __shared__ __align__(16) unsigned short Bs[NSTAGE][128][STR];
    __shared__ int rowoff[128];

    const int tid = threadIdx.x;
    const int row0 = blockIdx.y * 128, col0 = blockIdx.x * 128;
    const int lane = tid & 31, wid = tid >> 5;
    const int wm = wid >> 2, wn = wid & 3;

    if (tid < 128) rowoff[tid] = row_to_pixel(row0 + tid) * 256;
    __syncthreads();

    float acc[16][4];
#pragma unroll
    for (int i = 0; i < 16; i++)
#pragma unroll
        for (int j = 0; j < 4; j++) acc[i][j] = 0.0f;

    const int srow = tid >> 1, sseg = (tid & 1) * 2;   // 2 of 4 16B segs per row

    auto stage = [&](int buf, int kt) {
        const int k16 = kt * 16;
#pragma unroll
        for (int q = 0; q < 2; q++) {
            int seg = sseg + q;
            cp16(s2u(&As[buf][srow][seg * 8]), &g_xbf[(size_t)rowoff[srow] + k16 + seg * 4]);
            cp16(s2u(&Bs[buf][srow][seg * 8]), &g_wqkv_t[(size_t)(col0 + srow) * 256 + k16 + seg * 4]);
        }
    };

    stage(0, 0); cp_commit();
    stage(1, 1); cp_commit();

    const unsigned a_base = s2u(&As[0][0][0]);
    const unsigned b_base = s2u(&Bs[0][0][0]);
    const unsigned bufsz = 128 * STR * 2;
    const int a_row = wm * 64 + (lane & 15);
    const int a_colB = (lane >> 4) * 16;
    const int b_row = wn * 32 + ((lane >> 4) & 1) * 8 + (lane & 7);
    const int b_colB = ((lane >> 3) & 1) * 16;

    int buf = 0, sbuf = 2;
#pragma unroll 1
    for (int t = 0; t < 16; t++) {
        if (t < 15) cp_wait1(); else cp_wait0();
        __syncthreads();
        if (t < 14) { stage(sbuf, t + 2); cp_commit(); }
        const unsigned ab = a_base + buf * bufsz;
        const unsigned bb = b_base + buf * bufsz;
#pragma unroll
        for (int ks = 0; ks < 2; ks++) {
            unsigned afr[4][4], bfr[2][4];
#pragma unroll
            for (int mt = 0; mt < 4; mt++)
                ldsm4(afr[mt], ab + (unsigned)((a_row + mt * 16) * (STR * 2) + ks * 32 + a_colB));
#pragma unroll
            for (int n2 = 0; n2 < 2; n2++)
                ldsm4(bfr[n2], bb + (unsigned)((b_row + n2 * 16) * (STR * 2) + ks * 32 + b_colB));
#pragma unroll
            for (int mt = 0; mt < 4; mt++)
#pragma unroll
                for (int nt = 0; nt < 4; nt++)
                    mma_bf16(acc[mt * 4 + nt], afr[mt], &bfr[nt >> 1][(nt & 1) * 2]);
        }
        buf = (buf == NSTAGE - 1) ? 0 : buf + 1;
        sbuf = (sbuf == NSTAGE - 1) ? 0 : sbuf + 1;
    }

    // epilogue: +bias, pack bf16, scatter into g_qkvb
#pragma unroll
    for (int mt = 0; mt < 4; mt++) {
#pragma unroll
        for (int half = 0; half < 2; half++) {
            int r = row0 + wm * 64 + mt * 16 + (lane >> 2) + half * 8;
            int win = r / NTOK, tok = r - win * NTOK;
#pragma unroll
            for (int nt = 0; nt < 4; nt++) {
                int c = col0 + wn * 32 + nt * 8 + (lane & 3) * 2;
                int s = c >> 9, head = (c >> 5) & 15, dd = c & 31;
                size_t ub = (((size_t)s * NWIN + win) * HEADS + head) * (NTOK * 16)
                          + (size_t)tok * 16 + (dd >> 1);
                float lo = acc[mt * 4 + nt][half * 2]     + bias[c];
                float hi = acc[mt * 4 + nt][half * 2 + 1] + bias[c + 1];
                g_qkvb[ub] = pkbf(lo, hi);
            }
        }
    }
}

// ---------------------------------------------------------------------------
// Kernel 2: windowed attention, bf16 IO, f32x2 math, warp-per-row softmax.
// ---------------------------------------------------------------------------
__global__ __launch_bounds__(256) void attn_kernel(const float* __restrict__ table) {
    const int wh = blockIdx.x;
    const int win = wh >> 4;
    const int head = wh & 15;
    const int tid = threadIdx.x;
    const int lane = tid & 31, wid = tid >> 5;

    __shared__ float qs[NTOK * 36];
    __shared__ float ks_[NTOK * 36];
    __shared__ float vs[NTOK * 36];
    __shared__ float S[NTOK * NTOK];
    __shared__ float tbl[169];
    __shared__ int reg[NTOK];

    const size_t SOFF2 = (size_t)NWIN * HEADS * NTOK * 16;
    const size_t base2 = ((size_t)win * HEADS + head) * (NTOK * 16);

    if (tid < 196) {
        int t = tid >> 2, ub = (tid & 3) * 4, dd = (tid & 3) * 8;
        uint4 q4 = *reinterpret_cast<const uint4*>(&g_qkvb[base2 + t * 16 + ub]);
        uint4 k4 = *reinterpret_cast<const uint4*>(&g_qkvb[SOFF2 + base2 + t * 16 + ub]);
        uint4 v4 = *reinterpret_cast<const uint4*>(&g_qkvb[2 * SOFF2 + base2 + t * 16 + ub]);
        expand8(&qs[t * 36 + dd], q4);
        expand8(&ks_[t * 36 + dd], k4);
        expand8(&vs[t * 36 + dd], v4);
    }
    if (tid < 169) tbl[tid] = table[tid * HEADS + head];
    if (tid >= 200 && tid < 200 + NTOK) {
        int t = tid - 200;
        int wy = (win >> 3) & 7, wx = win & 7;
        int ty = t / WSZ, tx = t - ty * WSZ;
        int hs = wy * WSZ + ty, ws = wx * WSZ + tx;
        int rh = (hs < 49) ? 0 : ((hs < 53) ? 1 : 2);
        int rw = (ws < 49) ? 0 : ((ws < 53) ? 1 : 2);
        reg[t] = rh * 3 + rw;
    }
    __syncthreads();

    const float scale = 0.17677669529663687f;

    if (tid < 196) {
        const int i = tid >> 2, jq = tid & 3;
        const int j0 = jq * 13, j1 = (jq == 3) ? 49 : j0 + 13;
        ull qv[16];
#pragma unroll
        for (int p = 0; p < 16; p++)
            qv[p] = *reinterpret_cast<const ull*>(&qs[i * 36 + 2 * p]);
        const int iy = i / WSZ, ix = i - iy * WSZ;
        const int ri = reg[i];
        for (int j = j0; j < j1; j++) {
            ull a0 = 0ull, a1 = 0ull;
            const ull* kp = reinterpret_cast<const ull*>(&ks_[j * 36]);
#pragma unroll
            for (int p = 0; p < 16; p += 2) { fma2(a0, qv[p], kp[p]); fma2(a1, qv[p+1], kp[p+1]); }
            float2 f0 = unpack2(a0), f1 = unpack2(a1);
            float d = (f0.x + f0.y) + (f1.x + f1.y);
            int jy = j / WSZ, jx = j - jy * WSZ;
            int ridx = (iy - jy + 6) * 13 + (ix - jx + 6);
            float m = (ri != reg[j]) ? -100.0f : 0.0f;
            S[i * NTOK + j] = d * scale + tbl[ridx] + m;
        }
    }
    __syncthreads();

    // warp-per-row softmax: 8 warps cover 49 rows
    for (int i = wid; i < NTOK; i += 8) {
        float v0 = S[i * NTOK + lane];
        float v1 = (lane + 32 < NTOK) ? S[i * NTOK + lane + 32] : -1e30f;
        float mx = fmaxf(v0, v1);
#pragma unroll
        for (int off = 16; off; off >>= 1)
            mx = fmaxf(mx, __shfl_xor_sync(0xffffffffu, mx, off));
        float e0 = (lane < NTOK) ? __expf(v0 - mx) : 0.0f;
        float e1 = (lane + 32 < NTOK) ? __expf(v1 - mx) : 0.0f;
        float sum = e0 + e1;
#pragma unroll
        for (int off = 16; off; off >>= 1)
            sum += __shfl_xor_sync(0xffffffffu, sum, off);
        float inv = 1.0f / sum;
        S[i * NTOK + lane] = e0 * inv;
        if (lane + 32 < NTOK) S[i * NTOK + lane + 32] = e1 * inv;
    }
    __syncthreads();

    for (int idx = tid; idx < 392; idx += 256) {
        int i = idx >> 3, dq = (idx & 7) * 4;
        ull o0 = 0ull, o1 = 0ull;
        const float* sp = &S[i * NTOK];
        for (int j = 0; j < NTOK; j++) {
            ull sv = pack2(sp[j]);
            const ull* vp = reinterpret_cast<const ull*>(&vs[j * 36 + dq]);
            fma2(o0, sv, vp[0]);
            fma2(o1, sv, vp[1]);
        }
        float2 a = unpack2(o0), b = unpack2(o1);
        uint2 ov = { pkbf(a.x, a.y), pkbf(b.x, b.y) };
        *reinterpret_cast<uint2*>(&g_attnb[((size_t)win * NTOK + i) * 256 + head * 16 + (dq >> 1)]) = ov;
    }
}

// ---------------------------------------------------------------------------
// Kernel 3: proj GEMM + window reverse + bias + residual (f32 out)
// ---------------------------------------------------------------------------
__global__ __launch_bounds__(256, 1) void proj_gemm(const float* __restrict__ x,
                                                    const float* __restrict__ bias,
                                                    float* __restrict__ out) {
    __shared__ __align__(16) unsigned short As[NSTAGE][128][STR];
    __shared__ __align__(16) unsigned short Bs[NSTAGE][128][STR];

    const int tid = threadIdx.x;
    const int row0 = blockIdx.y * 128, col0 = blockIdx.x * 128;
    const int lane = tid & 31, wid = tid >> 5;
    const int wm = wid >> 2, wn = wid & 3;

    float acc[16][4];
#pragma unroll
    for (int i = 0; i < 16; i++)
#pragma unroll
        for (int j = 0; j < 4; j++) acc[i][j] = 0.0f;

    const int srow = tid >> 1, sseg = (tid & 1) * 2;

    auto stage = [&](int buf, int kt) {
        const int k16 = kt * 16;
#pragma unroll
        for (int q = 0; q < 2; q++) {
            int seg = sseg + q;
            cp16(s2u(&As[buf][srow][seg * 8]), &g_attnb[(size_t)(row0 + srow) * 256 + k16 + seg * 4]);
            cp16(s2u(&Bs[buf][srow][seg * 8]), &g_wproj_t[(size_t)(col0 + srow) * 256 + k16 + seg * 4]);
        }
    };

    stage(0, 0); cp_commit();
    stage(1, 1); cp_commit();

    const unsigned a_base = s2u(&As[0][0][0]);
    const unsigned b_base = s2u(&Bs[0][0][0]);
    const unsigned bufsz = 128 * STR * 2;
    const int a_row = wm * 64 + (lane & 15);
    const int a_colB = (lane >> 4) * 16;
    const int b_row = wn * 32 + ((lane >> 4) & 1) * 8 + (lane & 7);
    const int b_colB = ((lane >> 3) & 1) * 16;

    int buf = 0, sbuf = 2;
#pragma unroll 1
    for (int t = 0; t < 16; t++) {
        if (t < 15) cp_wait1(); else cp_wait0();
        __syncthreads();
        if (t < 14) { stage(sbuf, t + 2); cp_commit(); }
        const unsigned ab = a_base + buf * bufsz;
        const unsigned bb = b_base + buf * bufsz;
#pragma unroll
        for (int ks = 0; ks < 2; ks++) {
            unsigned afr[4][4], bfr[2][4];
#pragma unroll
            for (int mt = 0; mt < 4; mt++)
                ldsm4(afr[mt], ab + (unsigned)((a_row + mt * 16) * (STR * 2) + ks * 32 + a_colB));
#pragma unroll
            for (int n2 = 0; n2 < 2; n2++)
                ldsm4(bfr[n2], bb + (unsigned)((b_row + n2 * 16) * (STR * 2) + ks * 32 + b_colB));
#pragma unroll
            for (int mt = 0; mt < 4; mt++)
#pragma unroll
                for (int nt = 0; nt < 4; nt++)
                    mma_bf16(acc[mt * 4 + nt], afr[mt], &bfr[nt >> 1][(nt & 1) * 2]);
        }
        buf = (buf == NSTAGE - 1) ? 0 : buf + 1;
        sbuf = (sbuf == NSTAGE - 1) ? 0 : sbuf + 1;
    }

#pragma unroll
    for (int mt = 0; mt < 4; mt++) {
#pragma unroll
        for (int half = 0; half < 2; half++) {
            int r = row0 + wm * 64 + mt * 16 + (lane >> 2) + half * 8;
            size_t pix = (size_t)row_to_pixel(r) * CDIM;
#pragma unroll
            for (int nt = 0; nt < 4; nt++) {
                int c = col0 + wn * 32 + nt * 8 + (lane & 3) * 2;
                float2 bv2 = *reinterpret_cast<const float2*>(bias + c);
                float2 xv  = *reinterpret_cast<const float2*>(x + pix + c);
                float2 ov;
                ov.x = xv.x + acc[mt * 4 + nt][half * 2]     + bv2.x;
                ov.y = xv.y + acc[mt * 4 + nt][half * 2 + 1] + bv2.y;
                *reinterpret_cast<float2*>(&out[pix + c]) = ov;
            }
        }
    }
}

extern "C" void kernel_launch(void* const* d_in, const int* in_sizes, int n_in,
                              void* d_out, int out_size) {
    const float* x      = (const float*)d_in[0];
    const float* qkv_w  = (const float*)d_in[1];
    const float* qkv_b  = (const float*)d_in[2];
    const float* proj_w = (const float*)d_in[3];
    const float* proj_b = (const float*)d_in[4];
    const float* table  = (const float*)d_in[5];
    float* out = (float*)d_out;

    cvt_x_kernel<<<(NPIX * 512 / 4) / 256, 256>>>(x);
    wtrans_kernel<<<1536, 256>>>(qkv_w, 1536, 0);
    wtrans_kernel<<<512, 256>>>(proj_w, 512, 1);

    qkv_gemm<<<dim3(12, 392), 256>>>(qkv_b);
    attn_kernel<<<NWIN * HEADS, 256>>>(table);
    proj_gemm<<<dim3(4, 392), 256>>>(x, proj_b, out);
}

// round 12
// speedup vs baseline: 1.5768x; 1.0644x over previous
#include <cuda_runtime.h>
#include <cuda_bf16.h>
#include <cstdint>

#define WSZ 7
#define SHIFT 3
#define HEADS 16
#define NTOK 49
#define CDIM 512
#define DHEAD 32
#define HH 56
#define NWIN 1024
#define MROWS (NWIN*NTOK)   // 50176
#define NPIX  MROWS

typedef unsigned long long ull;

__device__ unsigned g_xbf[(size_t)NPIX*256];              // x bf16 [pix][512]
__device__ unsigned g_wqkv_t[1536*256];                   // qkv_w^T bf16 [n][k]
__device__ unsigned g_wproj_t[512*256];                   // proj_w^T bf16 [n][k]
__device__ unsigned g_qkvb[(size_t)3*NWIN*HEADS*NTOK*16]; // qkv bf16 [s][win][head][tok][32]
__device__ unsigned g_attnb[(size_t)MROWS*256];           // attn out bf16 [row][512]

__device__ __forceinline__ int row_to_pixel(int r) {
    int win = r / NTOK, t = r - win * NTOK;
    int b  = win >> 6;
    int wy = (win >> 3) & 7;
    int wx = win & 7;
    int ty = t / WSZ, tx = t - ty * WSZ;
    int hs = wy * WSZ + ty;
    int ws = wx * WSZ + tx;
    int h = hs + SHIFT; if (h >= HH) h -= HH;
    int w = ws + SHIFT; if (w >= HH) w -= HH;
    return (b * HH + h) * HH + w;
}

__device__ __forceinline__ unsigned pkbf(float lo, float hi) {
    unsigned r; asm("cvt.rn.bf16x2.f32 %0, %1, %2;" : "=r"(r) : "f"(hi), "f"(lo)); return r;
}
__device__ __forceinline__ ull pack2(float x) {
    ull r; asm("mov.b64 %0, {%1, %1};" : "=l"(r) : "f"(x)); return r;
}
__device__ __forceinline__ void fma2(ull& d, ull a, ull b) {
    asm("fma.rn.f32x2 %0, %1, %2, %3;" : "=l"(d) : "l"(a), "l"(b), "l"(d));
}
__device__ __forceinline__ float2 unpack2(ull v) {
    float2 f; asm("mov.b64 {%0, %1}, %2;" : "=f"(f.x), "=f"(f.y) : "l"(v)); return f;
}
__device__ __forceinline__ void expand8(float* dst, uint4 v) {
    unsigned a[4] = {v.x, v.y, v.z, v.w};
#pragma unroll
    for (int i = 0; i < 4; i++) {
        dst[2*i]   = __uint_as_float(a[i] << 16);
        dst[2*i+1] = __uint_as_float(a[i] & 0xffff0000u);
    }
}
__device__ __forceinline__ unsigned s2u(const void* p) {
    return (unsigned)__cvta_generic_to_shared(p);
}
__device__ __forceinline__ void ldsm4(unsigned* r, unsigned a) {
    asm volatile("ldmatrix.sync.aligned.m8n8.x4.shared.b16 {%0,%1,%2,%3}, [%4];"
                 : "=r"(r[0]), "=r"(r[1]), "=r"(r[2]), "=r"(r[3]) : "r"(a));
}
__device__ __forceinline__ void mma_bf16(float* d, const unsigned* a, const unsigned* b) {
    asm volatile(
        "mma.sync.aligned.m16n8k16.row.col.f32.bf16.bf16.f32 "
        "{%0,%1,%2,%3}, {%4,%5,%6,%7}, {%8,%9}, {%0,%1,%2,%3};"
        : "+f"(d[0]), "+f"(d[1]), "+f"(d[2]), "+f"(d[3])
        : "r"(a[0]), "r"(a[1]), "r"(a[2]), "r"(a[3]), "r"(b[0]), "r"(b[1]));
}
__device__ __forceinline__ void cp16(unsigned dst, const void* src) {
    asm volatile("cp.async.cg.shared.global [%0], [%1], 16;" :: "r"(dst), "l"(src) : "memory");
}
__device__ __forceinline__ void cp_commit() { asm volatile("cp.async.commit_group;" ::: "memory"); }
__device__ __forceinline__ void cp_wait1()  { asm volatile("cp.async.wait_group 1;" ::: "memory"); }
__device__ __forceinline__ void cp_wait0()  { asm volatile("cp.async.wait_group 0;" ::: "memory"); }

#define STR 40   // smem row stride (bf16) = 80B -> conflict-free LDSM
#define NSTAGE 3

// ---------------------------------------------------------------------------
// Prepasses
// ---------------------------------------------------------------------------
__global__ void cvt_x_kernel(const float* __restrict__ x) {
    size_t i = (size_t)blockIdx.x * 256 + threadIdx.x;
    float4 v = *reinterpret_cast<const float4*>(x + i * 4);
    uint2 o = { pkbf(v.x, v.y), pkbf(v.z, v.w) };
    *reinterpret_cast<uint2*>(&g_xbf[i * 2]) = o;
}
__global__ void wtrans_kernel(const float* __restrict__ w, int ncols, int which) {
    int n = blockIdx.x, t = threadIdx.x;
    float a = w[(size_t)(2 * t)     * ncols + n];
    float b = w[(size_t)(2 * t + 1) * ncols + n];
    unsigned v = pkbf(a, b);
    if (which) g_wproj_t[n * 256 + t] = v; else g_wqkv_t[n * 256 + t] = v;
}

// ---------------------------------------------------------------------------
// Kernel 1: QKV GEMM. CTA 128x128, 512 threads, warp tile 32x32, 3-stage pipe.
// ---------------------------------------------------------------------------
__global__ __launch_bounds__(512, 1) void qkv_gemm(const float* __restrict__ bias) {
    __shared__ __align__(16) unsigned short As[NSTAGE][128][STR];
    __shared__ __align__(16) unsigned short Bs[NSTAGE][128][STR];
    __shared__ int rowoff[128];

    const int tid = threadIdx.x;
    const int row0 = blockIdx.y * 128, col0 = blockIdx.x * 128;
    const int lane = tid & 31, wid = tid >> 5;     // 16 warps
    const int wm = wid >> 2, wn = wid & 3;         // 4x4 warp grid

    if (tid < 128) rowoff[tid] = row_to_pixel(row0 + tid) * 256;
    __syncthreads();

    float acc[8][4];
#pragma unroll
    for (int i = 0; i < 8; i++)
#pragma unroll
        for (int j = 0; j < 4; j++) acc[i][j] = 0.0f;

    const int srow = tid >> 2, sseg = tid & 3;     // 1 seg of 16B per matrix

    auto stage = [&](int buf, int kt) {
        const int k16 = kt * 16;
        cp16(s2u(&As[buf][srow][sseg * 8]), &g_xbf[(size_t)rowoff[srow] + k16 + sseg * 4]);
        cp16(s2u(&Bs[buf][srow][sseg * 8]), &g_wqkv_t[(size_t)(col0 + srow) * 256 + k16 + sseg * 4]);
    };

    stage(0, 0); cp_commit();
    stage(1, 1); cp_commit();

    const unsigned a_base = s2u(&As[0][0][0]);
    const unsigned b_base = s2u(&Bs[0][0][0]);
    const unsigned bufsz = 128 * STR * 2;
    const int a_row = wm * 32 + (lane & 15);
    const int a_colB = (lane >> 4) * 16;
    const int b_row = wn * 32 + ((lane >> 4) & 1) * 8 + (lane & 7);
    const int b_colB = ((lane >> 3) & 1) * 16;

    int buf = 0, sbuf = 2;
#pragma unroll 1
    for (int t = 0; t < 16; t++) {
        if (t < 15) cp_wait1(); else cp_wait0();
        __syncthreads();
        if (t < 14) { stage(sbuf, t + 2); cp_commit(); }
        const unsigned ab = a_base + buf * bufsz;
        const unsigned bb = b_base + buf * bufsz;
#pragma unroll
        for (int ks = 0; ks < 2; ks++) {
            unsigned afr[2][4], bfr[2][4];
#pragma unroll
            for (int mt = 0; mt < 2; mt++)
                ldsm4(afr[mt], ab + (unsigned)((a_row + mt * 16) * (STR * 2) + ks * 32 + a_colB));
#pragma unroll
            for (int n2 = 0; n2 < 2; n2++)
                ldsm4(bfr[n2], bb + (unsigned)((b_row + n2 * 16) * (STR * 2) + ks * 32 + b_colB));
#pragma unroll
            for (int mt = 0; mt < 2; mt++)
#pragma unroll
                for (int nt = 0; nt < 4; nt++)
                    mma_bf16(acc[mt * 4 + nt], afr[mt], &bfr[nt >> 1][(nt & 1) * 2]);
        }
        buf = (buf == NSTAGE - 1) ? 0 : buf + 1;
        sbuf = (sbuf == NSTAGE - 1) ? 0 : sbuf + 1;
    }

    // epilogue: +bias, pack bf16, scatter into g_qkvb
#pragma unroll
    for (int mt = 0; mt < 2; mt++) {
#pragma unroll
        for (int half = 0; half < 2; half++) {
            int r = row0 + wm * 32 + mt * 16 + (lane >> 2) + half * 8;
            int win = r / NTOK, tok = r - win * NTOK;
#pragma unroll
            for (int nt = 0; nt < 4; nt++) {
                int c = col0 + wn * 32 + nt * 8 + (lane & 3) * 2;
                int s = c >> 9, head = (c >> 5) & 15, dd = c & 31;
                size_t ub = (((size_t)s * NWIN + win) * HEADS + head) * (NTOK * 16)
                          + (size_t)tok * 16 + (dd >> 1);
                float lo = acc[mt * 4 + nt][half * 2]     + bias[c];
                float hi = acc[mt * 4 + nt][half * 2 + 1] + bias[c + 1];
                g_qkvb[ub] = pkbf(lo, hi);
            }
        }
    }
}

// ---------------------------------------------------------------------------
// Kernel 2: windowed attention, bf16 IO, f32x2 math, warp-per-row softmax.
// ---------------------------------------------------------------------------
__global__ __launch_bounds__(256) void attn_kernel(const float* __restrict__ table) {
    const int wh = blockIdx.x;
    const int win = wh >> 4;
    const int head = wh & 15;
    const int tid = threadIdx.x;
    const int lane = tid & 31, wid = tid >> 5;

    __shared__ float qs[NTOK * 36];
    __shared__ float ks_[NTOK * 36];
    __shared__ float vs[NTOK * 36];
    __shared__ float S[NTOK * NTOK];
    __shared__ float tbl[169];
    __shared__ int reg[NTOK];

    const size_t SOFF2 = (size_t)NWIN * HEADS * NTOK * 16;
    const size_t base2 = ((size_t)win * HEADS + head) * (NTOK * 16);

    if (tid < 196) {
        int t = tid >> 2, ub = (tid & 3) * 4, dd = (tid & 3) * 8;
        uint4 q4 = *reinterpret_cast<const uint4*>(&g_qkvb[base2 + t * 16 + ub]);
        uint4 k4 = *reinterpret_cast<const uint4*>(&g_qkvb[SOFF2 + base2 + t * 16 + ub]);
        uint4 v4 = *reinterpret_cast<const uint4*>(&g_qkvb[2 * SOFF2 + base2 + t * 16 + ub]);
        expand8(&qs[t * 36 + dd], q4);
        expand8(&ks_[t * 36 + dd], k4);
        expand8(&vs[t * 36 + dd], v4);
    }
    if (tid < 169) tbl[tid] = table[tid * HEADS + head];
    if (tid >= 200 && tid < 200 + NTOK) {
        int t = tid - 200;
        int wy = (win >> 3) & 7, wx = win & 7;
        int ty = t / WSZ, tx = t - ty * WSZ;
        int hs = wy * WSZ + ty, ws = wx * WSZ + tx;
        int rh = (hs < 49) ? 0 : ((hs < 53) ? 1 : 2);
        int rw = (ws < 49) ? 0 : ((ws < 53) ? 1 : 2);
        reg[t] = rh * 3 + rw;
    }
    __syncthreads();

    const float scale = 0.17677669529663687f;

    if (tid < 196) {
        const int i = tid >> 2, jq = tid & 3;
        const int j0 = jq * 13, j1 = (jq == 3) ? 49 : j0 + 13;
        ull qv[16];
#pragma unroll
        for (int p = 0; p < 16; p++)
            qv[p] = *reinterpret_cast<const ull*>(&qs[i * 36 + 2 * p]);
        const int iy = i / WSZ, ix = i - iy * WSZ;
        const int ri = reg[i];
        for (int j = j0; j < j1; j++) {
            ull a0 = 0ull, a1 = 0ull;
            const ull* kp = reinterpret_cast<const ull*>(&ks_[j * 36]);
#pragma unroll
            for (int p = 0; p < 16; p += 2) { fma2(a0, qv[p], kp[p]); fma2(a1, qv[p+1], kp[p+1]); }
            float2 f0 = unpack2(a0), f1 = unpack2(a1);
            float d = (f0.x + f0.y) + (f1.x + f1.y);
            int jy = j / WSZ, jx = j - jy * WSZ;
            int ridx = (iy - jy + 6) * 13 + (ix - jx + 6);
            float m = (ri != reg[j]) ? -100.0f : 0.0f;
            S[i * NTOK + j] = d * scale + tbl[ridx] + m;
        }
    }
    __syncthreads();

    // warp-per-row softmax: 8 warps cover 49 rows
    for (int i = wid; i < NTOK; i += 8) {
        float v0 = S[i * NTOK + lane];
        float v1 = (lane + 32 < NTOK) ? S[i * NTOK + lane + 32] : -1e30f;
        float mx = fmaxf(v0, v1);
#pragma unroll
        for (int off = 16; off; off >>= 1)
            mx = fmaxf(mx, __shfl_xor_sync(0xffffffffu, mx, off));
        float e0 = (lane < NTOK) ? __expf(v0 - mx) : 0.0f;
        float e1 = (lane + 32 < NTOK) ? __expf(v1 - mx) : 0.0f;
        float sum = e0 + e1;
#pragma unroll
        for (int off = 16; off; off >>= 1)
            sum += __shfl_xor_sync(0xffffffffu, sum, off);
        float inv = 1.0f / sum;
        S[i * NTOK + lane] = e0 * inv;
        if (lane + 32 < NTOK) S[i * NTOK + lane + 32] = e1 * inv;
    }
    __syncthreads();

    for (int idx = tid; idx < 392; idx += 256) {
        int i = idx >> 3, dq = (idx & 7) * 4;
        ull o0 = 0ull, o1 = 0ull;
        const float* sp = &S[i * NTOK];
        for (int j = 0; j < NTOK; j++) {
            ull sv = pack2(sp[j]);
            const ull* vp = reinterpret_cast<const ull*>(&vs[j * 36 + dq]);
            fma2(o0, sv, vp[0]);
            fma2(o1, sv, vp[1]);
        }
        float2 a = unpack2(o0), b = unpack2(o1);
        uint2 ov = { pkbf(a.x, a.y), pkbf(b.x, b.y) };
        *reinterpret_cast<uint2*>(&g_attnb[((size_t)win * NTOK + i) * 256 + head * 16 + (dq >> 1)]) = ov;
    }
}

// ---------------------------------------------------------------------------
// Kernel 3: proj GEMM + window reverse + bias + residual (f32 out)
// ---------------------------------------------------------------------------
__global__ __launch_bounds__(512, 1) void proj_gemm(const float* __restrict__ x,
                                                    const float* __restrict__ bias,
                                                    float* __restrict__ out) {
    __shared__ __align__(16) unsigned short As[NSTAGE][128][STR];
    __shared__ __align__(16) unsigned short Bs[NSTAGE][128][STR];

    const int tid = threadIdx.x;
    const int row0 = blockIdx.y * 128, col0 = blockIdx.x * 128;
    const int lane = tid & 31, wid = tid >> 5;
    const int wm = wid >> 2, wn = wid & 3;

    float acc[8][4];
#pragma unroll
    for (int i = 0; i < 8; i++)
#pragma unroll
        for (int j = 0; j < 4; j++) acc[i][j] = 0.0f;

    const int srow = tid >> 2, sseg = tid & 3;

    auto stage = [&](int buf, int kt) {
        const int k16 = kt * 16;
        cp16(s2u(&As[buf][srow][sseg * 8]), &g_attnb[(size_t)(row0 + srow) * 256 + k16 + sseg * 4]);
        cp16(s2u(&Bs[buf][srow][sseg * 8]), &g_wproj_t[(size_t)(col0 + srow) * 256 + k16 + sseg * 4]);
    };

    stage(0, 0); cp_commit();
    stage(1, 1); cp_commit();

    const unsigned a_base = s2u(&As[0][0][0]);
    const unsigned b_base = s2u(&Bs[0][0][0]);
    const unsigned bufsz = 128 * STR * 2;
    const int a_row = wm * 32 + (lane & 15);
    const int a_colB = (lane >> 4) * 16;
    const int b_row = wn * 32 + ((lane >> 4) & 1) * 8 + (lane & 7);
    const int b_colB = ((lane >> 3) & 1) * 16;

    int buf = 0, sbuf = 2;
#pragma unroll 1
    for (int t = 0; t < 16; t++) {
        if (t < 15) cp_wait1(); else cp_wait0();
        __syncthreads();
        if (t < 14) { stage(sbuf, t + 2); cp_commit(); }
        const unsigned ab = a_base + buf * bufsz;
        const unsigned bb = b_base + buf * bufsz;
#pragma unroll
        for (int ks = 0; ks < 2; ks++) {
            unsigned afr[2][4], bfr[2][4];
#pragma unroll
            for (int mt = 0; mt < 2; mt++)
                ldsm4(afr[mt], ab + (unsigned)((a_row + mt * 16) * (STR * 2) + ks * 32 + a_colB));
#pragma unroll
            for (int n2 = 0; n2 < 2; n2++)
                ldsm4(bfr[n2], bb + (unsigned)((b_row + n2 * 16) * (STR * 2) + ks * 32 + b_colB));
#pragma unroll
            for (int mt = 0; mt < 2; mt++)
#pragma unroll
                for (int nt = 0; nt < 4; nt++)
                    mma_bf16(acc[mt * 4 + nt], afr[mt], &bfr[nt >> 1][(nt & 1) * 2]);
        }
        buf = (buf == NSTAGE - 1) ? 0 : buf + 1;
        sbuf = (sbuf == NSTAGE - 1) ? 0 : sbuf + 1;
    }

#pragma unroll
    for (int mt = 0; mt < 2; mt++) {
#pragma unroll
        for (int half = 0; half < 2; half++) {
            int r = row0 + wm * 32 + mt * 16 + (lane >> 2) + half * 8;
            size_t pix = (size_t)row_to_pixel(r) * CDIM;
#pragma unroll
            for (int nt = 0; nt < 4; nt++) {
                int c = col0 + wn * 32 + nt * 8 + (lane & 3) * 2;
                float2 bv2 = *reinterpret_cast<const float2*>(bias + c);
                float2 xv  = *reinterpret_cast<const float2*>(x + pix + c);
                float2 ov;
                ov.x = xv.x + acc[mt * 4 + nt][half * 2]     + bv2.x;
                ov.y = xv.y + acc[mt * 4 + nt][half * 2 + 1] + bv2.y;
                *reinterpret_cast<float2*>(&out[pix + c]) = ov;
            }
        }
    }
}

extern "C" void kernel_launch(void* const* d_in, const int* in_sizes, int n_in,
                              void* d_out, int out_size) {
    const float* x      = (const float*)d_in[0];
    const float* qkv_w  = (const float*)d_in[1];
    const float* qkv_b  = (const float*)d_in[2];
    const float* proj_w = (const float*)d_in[3];
    const float* proj_b = (const float*)d_in[4];
    const float* table  = (const float*)d_in[5];
    float* out = (float*)d_out;

    cvt_x_kernel<<<(NPIX * 512 / 4) / 256, 256>>>(x);
    wtrans_kernel<<<1536, 256>>>(qkv_w, 1536, 0);
    wtrans_kernel<<<512, 256>>>(proj_w, 512, 1);

    qkv_gemm<<<dim3(12, 392), 512>>>(qkv_b);
    attn_kernel<<<NWIN * HEADS, 256>>>(table);
    proj_gemm<<<dim3(4, 392), 512>>>(x, proj_b, out);
}

// round 14
// speedup vs baseline: 1.6229x; 1.0293x over previous
#include <cuda_runtime.h>
#include <cuda_bf16.h>
#include <cstdint>

#define WSZ 7
#define SHIFT 3
#define HEADS 16
#define NTOK 49
#define CDIM 512
#define DHEAD 32
#define HH 56
#define NWIN 1024
#define MROWS (NWIN*NTOK)   // 50176
#define NPIX  MROWS

typedef unsigned long long ull;

__device__ unsigned g_xbf[(size_t)NPIX*256];              // x bf16 [pix][512]
__device__ unsigned g_wqkv_t[1536*256];                   // qkv_w^T bf16 [n][k]
__device__ unsigned g_wproj_t[512*256];                   // proj_w^T bf16 [n][k]
__device__ unsigned g_qkvb[(size_t)3*NWIN*HEADS*NTOK*16]; // qkv bf16 [s][win][head][tok][32]
__device__ unsigned g_attnb[(size_t)MROWS*256];           // attn out bf16 [row][512]

__device__ __forceinline__ int row_to_pixel(int r) {
    int win = r / NTOK, t = r - win * NTOK;
    int b  = win >> 6;
    int wy = (win >> 3) & 7;
    int wx = win & 7;
    int ty = t / WSZ, tx = t - ty * WSZ;
    int hs = wy * WSZ + ty;
    int ws = wx * WSZ + tx;
    int h = hs + SHIFT; if (h >= HH) h -= HH;
    int w = ws + SHIFT; if (w >= HH) w -= HH;
    return (b * HH + h) * HH + w;
}

__device__ __forceinline__ unsigned pkbf(float lo, float hi) {
    unsigned r; asm("cvt.rn.bf16x2.f32 %0, %1, %2;" : "=r"(r) : "f"(hi), "f"(lo)); return r;
}
__device__ __forceinline__ unsigned s2u(const void* p) {
    return (unsigned)__cvta_generic_to_shared(p);
}
__device__ __forceinline__ void ldsm4(unsigned* r, unsigned a) {
    asm volatile("ldmatrix.sync.aligned.m8n8.x4.shared.b16 {%0,%1,%2,%3}, [%4];"
                 : "=r"(r[0]), "=r"(r[1]), "=r"(r[2]), "=r"(r[3]) : "r"(a));
}
__device__ __forceinline__ void ldsm4t(unsigned* r, unsigned a) {
    asm volatile("ldmatrix.sync.aligned.m8n8.x4.trans.shared.b16 {%0,%1,%2,%3}, [%4];"
                 : "=r"(r[0]), "=r"(r[1]), "=r"(r[2]), "=r"(r[3]) : "r"(a));
}
__device__ __forceinline__ void mma_bf16(float* d, const unsigned* a, const unsigned* b) {
    asm volatile(
        "mma.sync.aligned.m16n8k16.row.col.f32.bf16.bf16.f32 "
        "{%0,%1,%2,%3}, {%4,%5,%6,%7}, {%8,%9}, {%0,%1,%2,%3};"
        : "+f"(d[0]), "+f"(d[1]), "+f"(d[2]), "+f"(d[3])
        : "r"(a[0]), "r"(a[1]), "r"(a[2]), "r"(a[3]), "r"(b[0]), "r"(b[1]));
}
__device__ __forceinline__ void cp16(unsigned dst, const void* src) {
    asm volatile("cp.async.cg.shared.global [%0], [%1], 16;" :: "r"(dst), "l"(src) : "memory");
}
__device__ __forceinline__ void cp_commit() { asm volatile("cp.async.commit_group;" ::: "memory"); }
__device__ __forceinline__ void cp_wait1()  { asm volatile("cp.async.wait_group 1;" ::: "memory"); }
__device__ __forceinline__ void cp_wait0()  { asm volatile("cp.async.wait_group 0;" ::: "memory"); }

#define STR 40   // smem row stride (bf16) = 80B -> conflict-free LDSM, 16B-aligned rows
#define NSTAGE 3

// ---------------------------------------------------------------------------
// Prepasses
// ---------------------------------------------------------------------------
__global__ void cvt_x_kernel(const float* __restrict__ x) {
    size_t i = (size_t)blockIdx.x * 256 + threadIdx.x;
    float4 v = *reinterpret_cast<const float4*>(x + i * 4);
    uint2 o = { pkbf(v.x, v.y), pkbf(v.z, v.w) };
    *reinterpret_cast<uint2*>(&g_xbf[i * 2]) = o;
}
__global__ void wtrans_kernel(const float* __restrict__ w, int ncols, int which) {
    int n = blockIdx.x, t = threadIdx.x;
    float a = w[(size_t)(2 * t)     * ncols + n];
    float b = w[(size_t)(2 * t + 1) * ncols + n];
    unsigned v = pkbf(a, b);
    if (which) g_wproj_t[n * 256 + t] = v; else g_wqkv_t[n * 256 + t] = v;
}

// ---------------------------------------------------------------------------
// Kernel 1: QKV GEMM. CTA 128x128, 512 threads, warp tile 32x32, 3-stage pipe.
// ---------------------------------------------------------------------------
__global__ __launch_bounds__(512, 1) void qkv_gemm(const float* __restrict__ bias) {
    __shared__ __align__(16) unsigned short As[NSTAGE][128][STR];
    __shared__ __align__(16) unsigned short Bs[NSTAGE][128][STR];
    __shared__ int rowoff[128];

    const int tid = threadIdx.x;
    const int row0 = blockIdx.y * 128, col0 = blockIdx.x * 128;
    const int lane = tid & 31, wid = tid >> 5;
    const int wm = wid >> 2, wn = wid & 3;

    if (tid < 128) rowoff[tid] = row_to_pixel(row0 + tid) * 256;
    __syncthreads();

    float acc[8][4];
#pragma unroll
    for (int i = 0; i < 8; i++)
#pragma unroll
        for (int j = 0; j < 4; j++) acc[i][j] = 0.0f;

    const int srow = tid >> 2, sseg = tid & 3;

    auto stage = [&](int buf, int kt) {
        const int k16 = kt * 16;
        cp16(s2u(&As[buf][srow][sseg * 8]), &g_xbf[(size_t)rowoff[srow] + k16 + sseg * 4]);
        cp16(s2u(&Bs[buf][srow][sseg * 8]), &g_wqkv_t[(size_t)(col0 + srow) * 256 + k16 + sseg * 4]);
    };

    stage(0, 0); cp_commit();
    stage(1, 1); cp_commit();

    const unsigned a_base = s2u(&As[0][0][0]);
    const unsigned b_base = s2u(&Bs[0][0][0]);
    const unsigned bufsz = 128 * STR * 2;
    const int a_row = wm * 32 + (lane & 15);
    const int a_colB = (lane >> 4) * 16;
    const int b_row = wn * 32 + ((lane >> 4) & 1) * 8 + (lane & 7);
    const int b_colB = ((lane >> 3) & 1) * 16;

    int buf = 0, sbuf = 2;
#pragma unroll 1
    for (int t = 0; t < 16; t++) {
        if (t < 15) cp_wait1(); else cp_wait0();
        __syncthreads();
        if (t < 14) { stage(sbuf, t + 2); cp_commit(); }
        const unsigned ab = a_base + buf * bufsz;
        const unsigned bb = b_base + buf * bufsz;
#pragma unroll
        for (int ks = 0; ks < 2; ks++) {
            unsigned afr[2][4], bfr[2][4];
#pragma unroll
            for (int mt = 0; mt < 2; mt++)
                ldsm4(afr[mt], ab + (unsigned)((a_row + mt * 16) * (STR * 2) + ks * 32 + a_colB));
#pragma unroll
            for (int n2 = 0; n2 < 2; n2++)
                ldsm4(bfr[n2], bb + (unsigned)((b_row + n2 * 16) * (STR * 2) + ks * 32 + b_colB));
#pragma unroll
            for (int mt = 0; mt < 2; mt++)
#pragma unroll
                for (int nt = 0; nt < 4; nt++)
                    mma_bf16(acc[mt * 4 + nt], afr[mt], &bfr[nt >> 1][(nt & 1) * 2]);
        }
        buf = (buf == NSTAGE - 1) ? 0 : buf + 1;
        sbuf = (sbuf == NSTAGE - 1) ? 0 : sbuf + 1;
    }

#pragma unroll
    for (int mt = 0; mt < 2; mt++) {
#pragma unroll
        for (int half = 0; half < 2; half++) {
            int r = row0 + wm * 32 + mt * 16 + (lane >> 2) + half * 8;
            int win = r / NTOK, tok = r - win * NTOK;
#pragma unroll
            for (int nt = 0; nt < 4; nt++) {
                int c = col0 + wn * 32 + nt * 8 + (lane & 3) * 2;
                int s = c >> 9, head = (c >> 5) & 15, dd = c & 31;
                size_t ub = (((size_t)s * NWIN + win) * HEADS + head) * (NTOK * 16)
                          + (size_t)tok * 16 + (dd >> 1);
                float lo = acc[mt * 4 + nt][half * 2]     + bias[c];
                float hi = acc[mt * 4 + nt][half * 2 + 1] + bias[c + 1];
                g_qkvb[ub] = pkbf(lo, hi);
            }
        }
    }
}

// ---------------------------------------------------------------------------
// Kernel 2: tensor-core windowed attention. Block = (window, 4 heads),
// 8 warps, 2 warps per head (m-halves). Q/K/V padded 49->64 rows in smem.
// ---------------------------------------------------------------------------
__global__ __launch_bounds__(256) void attn_kernel(const float* __restrict__ table) {
    const int win = blockIdx.x;
    const int hg  = blockIdx.y;          // head group (4 heads)
    const int tid = threadIdx.x;
    const int lane = tid & 31, wid = tid >> 5;
    const int hh = wid >> 1;             // head within group
    const int half = wid & 1;            // m-half (rows 0-31 / 32-63)

    __shared__ __align__(16) unsigned short Qs[4][64][STR];
    __shared__ __align__(16) unsigned short Ks[4][64][STR];
    __shared__ __align__(16) unsigned short Vs[4][64][STR];
    __shared__ unsigned short tblh[4][170];
    __shared__ signed char jy7[64], jx7[64], regt[64];

    const size_t SOFF2 = (size_t)NWIN * HEADS * NTOK * 16;

    // zero the pad rows 49..63 (first 16 uints of each row)
    for (int idx = tid; idx < 720; idx += 256) {
        int arr = idx / 240, rem = idx % 240;
        int h4 = rem / 60, rem2 = rem % 60;
        int row = 49 + rem2 / 4, c = rem2 % 4;
        unsigned short* p = (arr == 0) ? &Qs[h4][row][c * 8]
                          : (arr == 1) ? &Ks[h4][row][c * 8] : &Vs[h4][row][c * 8];
        *reinterpret_cast<uint4*>(p) = make_uint4(0, 0, 0, 0);
    }
    // load Q,K,V (4 heads x 49 rows x 4 uint4)
    for (int idx = tid; idx < 2352; idx += 256) {
        int arr = idx / 784, rem = idx % 784;
        int h4 = rem / 196, rem2 = rem % 196;
        int row = rem2 / 4, c = rem2 % 4;
        int head = hg * 4 + h4;
        const unsigned* src = &g_qkvb[(size_t)arr * SOFF2
            + (((size_t)win * HEADS + head) * NTOK + row) * 16 + c * 4];
        uint4 v = *reinterpret_cast<const uint4*>(src);
        unsigned short* p = (arr == 0) ? &Qs[h4][row][c * 8]
                          : (arr == 1) ? &Ks[h4][row][c * 8] : &Vs[h4][row][c * 8];
        *reinterpret_cast<uint4*>(p) = v;
    }
    // bias tables (bf16) per head
    for (int idx = tid; idx < 676; idx += 256) {
        int h4 = idx / 169, e = idx % 169;
        float b = table[e * HEADS + hg * 4 + h4];
        tblh[h4][e] = (unsigned short)(pkbf(b, b) & 0xffffu);
    }
    if (tid < 64) {
        int t = tid;
        if (t < 49) {
            int ty = t / 7, tx = t % 7;
            jy7[t] = (signed char)ty; jx7[t] = (signed char)tx;
            int wy = (win >> 3) & 7, wx = win & 7;
            int hs = wy * 7 + ty, ws = wx * 7 + tx;
            int rh2 = (hs < 49) ? 0 : ((hs < 53) ? 1 : 2);
            int rw2 = (ws < 49) ? 0 : ((ws < 53) ? 1 : 2);
            regt[t] = (signed char)(rh2 * 3 + rw2);
        } else { jy7[t] = 0; jx7[t] = 0; regt[t] = 0; }
    }
    __syncthreads();

    const unsigned short (*Qh)[STR] = Qs[hh];
    const unsigned short (*Kh)[STR] = Ks[hh];
    const unsigned short (*Vh)[STR] = Vs[hh];
    const int r = lane >> 2, cq = lane & 3;

    // ---- S = Q K^T : 2 m-tiles x 8 n-tiles ----
    float sc[2][8][4];
#pragma unroll
    for (int mt = 0; mt < 2; mt++)
#pragma unroll
        for (int nt = 0; nt < 8; nt++)
#pragma unroll
            for (int c = 0; c < 4; c++) sc[mt][nt][c] = 0.0f;

#pragma unroll
    for (int ks = 0; ks < 2; ks++) {
        unsigned afr[2][4], bfr[4][4];
#pragma unroll
        for (int mt = 0; mt < 2; mt++) {
            int arow = (half * 2 + mt) * 16 + (lane & 15);
            ldsm4(afr[mt], s2u(&Qh[arow][ks * 16 + (lane >> 4) * 8]));
        }
#pragma unroll
        for (int p = 0; p < 4; p++) {
            int brow = p * 16 + ((lane >> 4) & 1) * 8 + (lane & 7);
            ldsm4(bfr[p], s2u(&Kh[brow][ks * 16 + ((lane >> 3) & 1) * 8]));
        }
#pragma unroll
        for (int mt = 0; mt < 2; mt++)
#pragma unroll
            for (int nt = 0; nt < 8; nt++)
                mma_bf16(sc[mt][nt], afr[mt], &bfr[nt >> 1][(nt & 1) * 2]);
    }

    // ---- scale + bias + shift-mask + softmax (fragment registers) ----
    const float scale = 0.17677669529663687f;
#pragma unroll
    for (int mt = 0; mt < 2; mt++) {
        const int i0 = (half * 2 + mt) * 16 + r;
#pragma unroll
        for (int rh = 0; rh < 2; rh++) {
            const int i = i0 + rh * 8;
            const int ri = regt[i];
            const int iy = jy7[i], ix = jx7[i];
            float vals[16];
            float mx = -1e30f;
#pragma unroll
            for (int nt = 0; nt < 8; nt++)
#pragma unroll
                for (int cc = 0; cc < 2; cc++) {
                    int j = nt * 8 + cq * 2 + cc;
                    float v;
                    if (j < 49) {
                        int ridx = (iy - jy7[j] + 6) * 13 + (ix - jx7[j] + 6);
                        float b = __uint_as_float((unsigned)tblh[hh][ridx] << 16);
                        float m = (ri != regt[j]) ? -100.0f : 0.0f;
                        v = sc[mt][nt][rh * 2 + cc] * scale + b + m;
                    } else v = -1e30f;
                    vals[nt * 2 + cc] = v;
                    mx = fmaxf(mx, v);
                }
            mx = fmaxf(mx, __shfl_xor_sync(0xffffffffu, mx, 1));
            mx = fmaxf(mx, __shfl_xor_sync(0xffffffffu, mx, 2));
            float sum = 0.0f;
#pragma unroll
            for (int q2 = 0; q2 < 16; q2++) { vals[q2] = __expf(vals[q2] - mx); sum += vals[q2]; }
            sum += __shfl_xor_sync(0xffffffffu, sum, 1);
            sum += __shfl_xor_sync(0xffffffffu, sum, 2);
            float inv = 1.0f / sum;
#pragma unroll
            for (int nt = 0; nt < 8; nt++) {
                sc[mt][nt][rh * 2]     = vals[nt * 2]     * inv;
                sc[mt][nt][rh * 2 + 1] = vals[nt * 2 + 1] * inv;
            }
        }
    }

    // ---- P fragments (C m16n8 pairs -> A m16k16) ----
    unsigned pf[2][4][4];
#pragma unroll
    for (int mt = 0; mt < 2; mt++)
#pragma unroll
        for (int kc = 0; kc < 4; kc++) {
            pf[mt][kc][0] = pkbf(sc[mt][2 * kc][0],     sc[mt][2 * kc][1]);
            pf[mt][kc][1] = pkbf(sc[mt][2 * kc][2],     sc[mt][2 * kc][3]);
            pf[mt][kc][2] = pkbf(sc[mt][2 * kc + 1][0], sc[mt][2 * kc + 1][1]);
            pf[mt][kc][3] = pkbf(sc[mt][2 * kc + 1][2], sc[mt][2 * kc + 1][3]);
        }

    // ---- O = P V ----
    float oc[2][4][4];
#pragma unroll
    for (int mt = 0; mt < 2; mt++)
#pragma unroll
        for (int dt = 0; dt < 4; dt++)
#pragma unroll
            for (int c = 0; c < 4; c++) oc[mt][dt][c] = 0.0f;

#pragma unroll
    for (int kc = 0; kc < 4; kc++) {
        unsigned vfr[2][4];
#pragma unroll
        for (int dp = 0; dp < 2; dp++)
            ldsm4t(vfr[dp], s2u(&Vh[kc * 16 + (lane & 15)][dp * 16 + (lane >> 4) * 8]));
#pragma unroll
        for (int mt = 0; mt < 2; mt++)
#pragma unroll
            for (int dt = 0; dt < 4; dt++)
                mma_bf16(oc[mt][dt], pf[mt][kc], &vfr[dt >> 1][(dt & 1) * 2]);
    }

    // ---- store O (bf16 pairs) ----
    const int head = hg * 4 + hh;
#pragma unroll
    for (int mt = 0; mt < 2; mt++) {
        const int i0 = (half * 2 + mt) * 16 + r;
#pragma unroll
        for (int rh = 0; rh < 2; rh++) {
            const int i = i0 + rh * 8;
            if (i < NTOK) {
                size_t rowb = ((size_t)win * NTOK + i) * 256 + head * 16;
#pragma unroll
                for (int dt = 0; dt < 4; dt++)
                    g_attnb[rowb + dt * 4 + cq] = pkbf(oc[mt][dt][rh * 2], oc[mt][dt][rh * 2 + 1]);
            }
        }
    }
}

// ---------------------------------------------------------------------------
// Kernel 3: proj GEMM + window reverse + bias + residual (f32 out)
// ---------------------------------------------------------------------------
__global__ __launch_bounds__(512, 1) void proj_gemm(const float* __restrict__ x,
                                                    const float* __restrict__ bias,
                                                    float* __restrict__ out) {
    __shared__ __align__(16) unsigned short As[NSTAGE][128][STR];
    __shared__ __align__(16) unsigned short Bs[NSTAGE][128][STR];

    const int tid = threadIdx.x;
    const int row0 = blockIdx.y * 128, col0 = blockIdx.x * 128;
    const int lane = tid & 31, wid = tid >> 5;
    const int wm = wid >> 2, wn = wid & 3;

    float acc[8][4];
#pragma unroll
    for (int i = 0; i < 8; i++)
#pragma unroll
        for (int j = 0; j < 4; j++) acc[i][j] = 0.0f;

    const int srow = tid >> 2, sseg = tid & 3;

    auto stage = [&](int buf, int kt) {
        const int k16 = kt * 16;
        cp16(s2u(&As[buf][srow][sseg * 8]), &g_attnb[(size_t)(row0 + srow) * 256 + k16 + sseg * 4]);
        cp16(s2u(&Bs[buf][srow][sseg * 8]), &g_wproj_t[(size_t)(col0 + srow) * 256 + k16 + sseg * 4]);
    };

    stage(0, 0); cp_commit();
    stage(1, 1); cp_commit();

    const unsigned a_base = s2u(&As[0][0][0]);
    const unsigned b_base = s2u(&Bs[0][0][0]);
    const unsigned bufsz = 128 * STR * 2;
    const int a_row = wm * 32 + (lane & 15);
    const int a_colB = (lane >> 4) * 16;
    const int b_row = wn * 32 + ((lane >> 4) & 1) * 8 + (lane & 7);
    const int b_colB = ((lane >> 3) & 1) * 16;

    int buf = 0, sbuf = 2;
#pragma unroll 1
    for (int t = 0; t < 16; t++) {
        if (t < 15) cp_wait1(); else cp_wait0();
        __syncthreads();
        if (t < 14) { stage(sbuf, t + 2); cp_commit(); }
        const unsigned ab = a_base + buf * bufsz;
        const unsigned bb = b_base + buf * bufsz;
#pragma unroll
        for (int ks = 0; ks < 2; ks++) {
            unsigned afr[2][4], bfr[2][4];
#pragma unroll
            for (int mt = 0; mt < 2; mt++)
                ldsm4(afr[mt], ab + (unsigned)((a_row + mt * 16) * (STR * 2) + ks * 32 + a_colB));
#pragma unroll
            for (int n2 = 0; n2 < 2; n2++)
                ldsm4(bfr[n2], bb + (unsigned)((b_row + n2 * 16) * (STR * 2) + ks * 32 + b_colB));
#pragma unroll
            for (int mt = 0; mt < 2; mt++)
#pragma unroll
                for (int nt = 0; nt < 4; nt++)
                    mma_bf16(acc[mt * 4 + nt], afr[mt], &bfr[nt >> 1][(nt & 1) * 2]);
        }
        buf = (buf == NSTAGE - 1) ? 0 : buf + 1;
        sbuf = (sbuf == NSTAGE - 1) ? 0 : sbuf + 1;
    }

#pragma unroll
    for (int mt = 0; mt < 2; mt++) {
#pragma unroll
        for (int half = 0; half < 2; half++) {
            int r = row0 + wm * 32 + mt * 16 + (lane >> 2) + half * 8;
            size_t pix = (size_t)row_to_pixel(r) * CDIM;
#pragma unroll
            for (int nt = 0; nt < 4; nt++) {
                int c = col0 + wn * 32 + nt * 8 + (lane & 3) * 2;
                float2 bv2 = *reinterpret_cast<const float2*>(bias + c);
                float2 xv  = *reinterpret_cast<const float2*>(x + pix + c);
                float2 ov;
                ov.x = xv.x + acc[mt * 4 + nt][half * 2]     + bv2.x;
                ov.y = xv.y + acc[mt * 4 + nt][half * 2 + 1] + bv2.y;
                *reinterpret_cast<float2*>(&out[pix + c]) = ov;
            }
        }
    }
}

extern "C" void kernel_launch(void* const* d_in, const int* in_sizes, int n_in,
                              void* d_out, int out_size) {
    const float* x      = (const float*)d_in[0];
    const float* qkv_w  = (const float*)d_in[1];
    const float* qkv_b  = (const float*)d_in[2];
    const float* proj_w = (const float*)d_in[3];
    const float* proj_b = (const float*)d_in[4];
    const float* table  = (const float*)d_in[5];
    float* out = (float*)d_out;

    cvt_x_kernel<<<(NPIX * 512 / 4) / 256, 256>>>(x);
    wtrans_kernel<<<1536, 256>>>(qkv_w, 1536, 0);
    wtrans_kernel<<<512, 256>>>(proj_w, 512, 1);

    qkv_gemm<<<dim3(12, 392), 512>>>(qkv_b);
    attn_kernel<<<dim3(NWIN, 4), 256>>>(table);
    proj_gemm<<<dim3(4, 392), 512>>>(x, proj_b, out);
}

// round 16
// speedup vs baseline: 2.4627x; 1.5175x over previous
#include <cuda_runtime.h>
#include <cuda_bf16.h>
#include <cstdint>

#define WSZ 7
#define SHIFT 3
#define HEADS 16
#define NTOK 49
#define CDIM 512
#define DHEAD 32
#define HH 56
#define NWIN 1024
#define MROWS (NWIN*NTOK)   // 50176
#define NPIX  MROWS

typedef unsigned long long ull;

__device__ unsigned g_xbf[(size_t)NPIX*256];              // x bf16 [pix][512]
__device__ unsigned g_wqkv_t[1536*256];                   // qkv_w^T bf16 [n][k]
__device__ unsigned g_wproj_t[512*256];                   // proj_w^T bf16 [n][k]
__device__ unsigned g_qkvb[(size_t)3*NWIN*HEADS*NTOK*16]; // qkv bf16 [s][win][head][tok][32]
__device__ unsigned g_attnb[(size_t)MROWS*256];           // attn out bf16 [row][512]

__device__ __forceinline__ int row_to_pixel(int r) {
    int win = r / NTOK, t = r - win * NTOK;
    int b  = win >> 6;
    int wy = (win >> 3) & 7;
    int wx = win & 7;
    int ty = t / WSZ, tx = t - ty * WSZ;
    int hs = wy * WSZ + ty;
    int ws = wx * WSZ + tx;
    int h = hs + SHIFT; if (h >= HH) h -= HH;
    int w = ws + SHIFT; if (w >= HH) w -= HH;
    return (b * HH + h) * HH + w;
}

__device__ __forceinline__ unsigned pkbf(float lo, float hi) {
    unsigned r; asm("cvt.rn.bf16x2.f32 %0, %1, %2;" : "=r"(r) : "f"(hi), "f"(lo)); return r;
}
__device__ __forceinline__ unsigned s2u(const void* p) {
    return (unsigned)__cvta_generic_to_shared(p);
}
__device__ __forceinline__ void ldsm4(unsigned* r, unsigned a) {
    asm volatile("ldmatrix.sync.aligned.m8n8.x4.shared.b16 {%0,%1,%2,%3}, [%4];"
                 : "=r"(r[0]), "=r"(r[1]), "=r"(r[2]), "=r"(r[3]) : "r"(a));
}
__device__ __forceinline__ void ldsm4t(unsigned* r, unsigned a) {
    asm volatile("ldmatrix.sync.aligned.m8n8.x4.trans.shared.b16 {%0,%1,%2,%3}, [%4];"
                 : "=r"(r[0]), "=r"(r[1]), "=r"(r[2]), "=r"(r[3]) : "r"(a));
}
__device__ __forceinline__ void mma_bf16(float* d, const unsigned* a, const unsigned* b) {
    asm volatile(
        "mma.sync.aligned.m16n8k16.row.col.f32.bf16.bf16.f32 "
        "{%0,%1,%2,%3}, {%4,%5,%6,%7}, {%8,%9}, {%0,%1,%2,%3};"
        : "+f"(d[0]), "+f"(d[1]), "+f"(d[2]), "+f"(d[3])
        : "r"(a[0]), "r"(a[1]), "r"(a[2]), "r"(a[3]), "r"(b[0]), "r"(b[1]));
}
__device__ __forceinline__ void cp16(unsigned dst, const void* src) {
    asm volatile("cp.async.cg.shared.global [%0], [%1], 16;" :: "r"(dst), "l"(src) : "memory");
}
__device__ __forceinline__ void cp_commit() { asm volatile("cp.async.commit_group;" ::: "memory"); }
__device__ __forceinline__ void cp_wait1()  { asm volatile("cp.async.wait_group 1;" ::: "memory"); }
__device__ __forceinline__ void cp_wait0()  { asm volatile("cp.async.wait_group 0;" ::: "memory"); }

#define STR 40   // smem row stride (bf16) = 80B -> conflict-free LDSM, 16B-aligned rows
#define NSTAGE 3

// ---------------------------------------------------------------------------
// Prepasses
// ---------------------------------------------------------------------------
__global__ void cvt_x_kernel(const float* __restrict__ x) {
    size_t i = (size_t)blockIdx.x * 256 + threadIdx.x;
    float4 v = *reinterpret_cast<const float4*>(x + i * 4);
    uint2 o = { pkbf(v.x, v.y), pkbf(v.z, v.w) };
    *reinterpret_cast<uint2*>(&g_xbf[i * 2]) = o;
}
__global__ void wtrans_kernel(const float* __restrict__ w, int ncols, int which) {
    int n = blockIdx.x, t = threadIdx.x;
    float a = w[(size_t)(2 * t)     * ncols + n];
    float b = w[(size_t)(2 * t + 1) * ncols + n];
    unsigned v = pkbf(a, b);
    if (which) g_wproj_t[n * 256 + t] = v; else g_wqkv_t[n * 256 + t] = v;
}

// ---------------------------------------------------------------------------
// Kernel 1: QKV GEMM. CTA 256x128, 512 threads, warp tile 64x32 (4x4 warps),
// 3-stage cp.async pipeline.
// ---------------------------------------------------------------------------
__global__ __launch_bounds__(512, 1) void qkv_gemm(const float* __restrict__ bias) {
    __shared__ __align__(16) unsigned short As[NSTAGE][256][STR];
    __shared__ __align__(16) unsigned short Bs[NSTAGE][128][STR];
    __shared__ int rowoff[256];

    const int tid = threadIdx.x;
    const int row0 = blockIdx.y * 256, col0 = blockIdx.x * 128;
    const int lane = tid & 31, wid = tid >> 5;
    const int wm = wid >> 2, wn = wid & 3;   // 4x4 warp grid, warp tile 64x32

    if (tid < 256) rowoff[tid] = row_to_pixel(row0 + tid) * 256;
    __syncthreads();

    float acc[16][4];
#pragma unroll
    for (int i = 0; i < 16; i++)
#pragma unroll
        for (int j = 0; j < 4; j++) acc[i][j] = 0.0f;

    const int a_sr = tid >> 1, a_ss = (tid & 1) * 2;   // A: 256 rows, 2 segs/thread
    const int b_sr = tid >> 2, b_ss = tid & 3;         // B: 128 rows, 1 seg/thread

    auto stage = [&](int buf, int kt) {
        const int k16 = kt * 16;
#pragma unroll
        for (int q = 0; q < 2; q++)
            cp16(s2u(&As[buf][a_sr][(a_ss + q) * 8]),
                 &g_xbf[(size_t)rowoff[a_sr] + k16 + (a_ss + q) * 4]);
        cp16(s2u(&Bs[buf][b_sr][b_ss * 8]),
             &g_wqkv_t[(size_t)(col0 + b_sr) * 256 + k16 + b_ss * 4]);
    };

    stage(0, 0); cp_commit();
    stage(1, 1); cp_commit();

    const unsigned a_base = s2u(&As[0][0][0]);
    const unsigned b_base = s2u(&Bs[0][0][0]);
    const unsigned a_sz = 256 * STR * 2, b_sz = 128 * STR * 2;
    const int a_row = wm * 64 + (lane & 15);
    const int a_colB = (lane >> 4) * 16;
    const int b_row = wn * 32 + ((lane >> 4) & 1) * 8 + (lane & 7);
    const int b_colB = ((lane >> 3) & 1) * 16;

    int buf = 0, sbuf = 2;
#pragma unroll 1
    for (int t = 0; t < 16; t++) {
        if (t < 15) cp_wait1(); else cp_wait0();
        __syncthreads();
        if (t < 14) { stage(sbuf, t + 2); cp_commit(); }
        const unsigned ab = a_base + buf * a_sz;
        const unsigned bb = b_base + buf * b_sz;
#pragma unroll
        for (int ks = 0; ks < 2; ks++) {
            unsigned afr[4][4], bfr[2][4];
#pragma unroll
            for (int mt = 0; mt < 4; mt++)
                ldsm4(afr[mt], ab + (unsigned)((a_row + mt * 16) * (STR * 2) + ks * 32 + a_colB));
#pragma unroll
            for (int n2 = 0; n2 < 2; n2++)
                ldsm4(bfr[n2], bb + (unsigned)((b_row + n2 * 16) * (STR * 2) + ks * 32 + b_colB));
#pragma unroll
            for (int mt = 0; mt < 4; mt++)
#pragma unroll
                for (int nt = 0; nt < 4; nt++)
                    mma_bf16(acc[mt * 4 + nt], afr[mt], &bfr[nt >> 1][(nt & 1) * 2]);
        }
        buf = (buf == NSTAGE - 1) ? 0 : buf + 1;
        sbuf = (sbuf == NSTAGE - 1) ? 0 : sbuf + 1;
    }

    // epilogue: +bias, pack bf16, scatter into g_qkvb
#pragma unroll
    for (int mt = 0; mt < 4; mt++) {
#pragma unroll
        for (int half = 0; half < 2; half++) {
            int r = row0 + wm * 64 + mt * 16 + (lane >> 2) + half * 8;
            int win = r / NTOK, tok = r - win * NTOK;
#pragma unroll
            for (int nt = 0; nt < 4; nt++) {
                int c = col0 + wn * 32 + nt * 8 + (lane & 3) * 2;
                int s = c >> 9, head = (c >> 5) & 15, dd = c & 31;
                size_t ub = (((size_t)s * NWIN + win) * HEADS + head) * (NTOK * 16)
                          + (size_t)tok * 16 + (dd >> 1);
                float lo = acc[mt * 4 + nt][half * 2]     + bias[c];
                float hi = acc[mt * 4 + nt][half * 2 + 1] + bias[c + 1];
                g_qkvb[ub] = pkbf(lo, hi);
            }
        }
    }
}

// ---------------------------------------------------------------------------
// Kernel 2: tensor-core windowed attention. Block = (window, 4 heads),
// 8 warps, 2 warps per head (m-halves). Q/K/V padded 49->64 rows in smem.
// ---------------------------------------------------------------------------
__global__ __launch_bounds__(256) void attn_kernel(const float* __restrict__ table) {
    const int win = blockIdx.x;
    const int hg  = blockIdx.y;
    const int tid = threadIdx.x;
    const int lane = tid & 31, wid = tid >> 5;
    const int hh = wid >> 1;
    const int half = wid & 1;

    __shared__ __align__(16) unsigned short Qs[4][64][STR];
    __shared__ __align__(16) unsigned short Ks[4][64][STR];
    __shared__ __align__(16) unsigned short Vs[4][64][STR];
    __shared__ unsigned short tblh[4][170];
    __shared__ signed char jy7[64], jx7[64], regt[64];

    const size_t SOFF2 = (size_t)NWIN * HEADS * NTOK * 16;

    for (int idx = tid; idx < 720; idx += 256) {
        int arr = idx / 240, rem = idx % 240;
        int h4 = rem / 60, rem2 = rem % 60;
        int row = 49 + rem2 / 4, c = rem2 % 4;
        unsigned short* p = (arr == 0) ? &Qs[h4][row][c * 8]
                          : (arr == 1) ? &Ks[h4][row][c * 8] : &Vs[h4][row][c * 8];
        *reinterpret_cast<uint4*>(p) = make_uint4(0, 0, 0, 0);
    }
    for (int idx = tid; idx < 2352; idx += 256) {
        int arr = idx / 784, rem = idx % 784;
        int h4 = rem / 196, rem2 = rem % 196;
        int row = rem2 / 4, c = rem2 % 4;
        int head = hg * 4 + h4;
        const unsigned* src = &g_qkvb[(size_t)arr * SOFF2
            + (((size_t)win * HEADS + head) * NTOK + row) * 16 + c * 4];
        uint4 v = *reinterpret_cast<const uint4*>(src);
        unsigned short* p = (arr == 0) ? &Qs[h4][row][c * 8]
                          : (arr == 1) ? &Ks[h4][row][c * 8] : &Vs[h4][row][c * 8];
        *reinterpret_cast<uint4*>(p) = v;
    }
    for (int idx = tid; idx < 676; idx += 256) {
        int h4 = idx / 169, e = idx % 169;
        float b = table[e * HEADS + hg * 4 + h4];
        tblh[h4][e] = (unsigned short)(pkbf(b, b) & 0xffffu);
    }
    if (tid < 64) {
        int t = tid;
        if (t < 49) {
            int ty = t / 7, tx = t % 7;
            jy7[t] = (signed char)ty; jx7[t] = (signed char)tx;
            int wy = (win >> 3) & 7, wx = win & 7;
            int hs = wy * 7 + ty, ws = wx * 7 + tx;
            int rh2 = (hs < 49) ? 0 : ((hs < 53) ? 1 : 2);
            int rw2 = (ws < 49) ? 0 : ((ws < 53) ? 1 : 2);
            regt[t] = (signed char)(rh2 * 3 + rw2);
        } else { jy7[t] = 0; jx7[t] = 0; regt[t] = 0; }
    }
    __syncthreads();

    const unsigned short (*Qh)[STR] = Qs[hh];
    const unsigned short (*Kh)[STR] = Ks[hh];
    const unsigned short (*Vh)[STR] = Vs[hh];
    const int r = lane >> 2, cq = lane & 3;

    float sc[2][8][4];
#pragma unroll
    for (int mt = 0; mt < 2; mt++)
#pragma unroll
        for (int nt = 0; nt < 8; nt++)
#pragma unroll
            for (int c = 0; c < 4; c++) sc[mt][nt][c] = 0.0f;

#pragma unroll
    for (int ks = 0; ks < 2; ks++) {
        unsigned afr[2][4], bfr[4][4];
#pragma unroll
        for (int mt = 0; mt < 2; mt++) {
            int arow = (half * 2 + mt) * 16 + (lane & 15);
            ldsm4(afr[mt], s2u(&Qh[arow][ks * 16 + (lane >> 4) * 8]));
        }
#pragma unroll
        for (int p = 0; p < 4; p++) {
            int brow = p * 16 + ((lane >> 4) & 1) * 8 + (lane & 7);
            ldsm4(bfr[p], s2u(&Kh[brow][ks * 16 + ((lane >> 3) & 1) * 8]));
        }
#pragma unroll
        for (int mt = 0; mt < 2; mt++)
#pragma unroll
            for (int nt = 0; nt < 8; nt++)
                mma_bf16(sc[mt][nt], afr[mt], &bfr[nt >> 1][(nt & 1) * 2]);
    }

    const float scale = 0.17677669529663687f;
#pragma unroll
    for (int mt = 0; mt < 2; mt++) {
        const int i0 = (half * 2 + mt) * 16 + r;
#pragma unroll
        for (int rh = 0; rh < 2; rh++) {
            const int i = i0 + rh * 8;
            const int ri = regt[i];
            const int iy = jy7[i], ix = jx7[i];
            float vals[16];
            float mx = -1e30f;
#pragma unroll
            for (int nt = 0; nt < 8; nt++)
#pragma unroll
                for (int cc = 0; cc < 2; cc++) {
                    int j = nt * 8 + cq * 2 + cc;
                    float v;
                    if (j < 49) {
                        int ridx = (iy - jy7[j] + 6) * 13 + (ix - jx7[j] + 6);
                        float b = __uint_as_float((unsigned)tblh[hh][ridx] << 16);
                        float m = (ri != regt[j]) ? -100.0f : 0.0f;
                        v = sc[mt][nt][rh * 2 + cc] * scale + b + m;
                    } else v = -1e30f;
                    vals[nt * 2 + cc] = v;
                    mx = fmaxf(mx, v);
                }
            mx = fmaxf(mx, __shfl_xor_sync(0xffffffffu, mx, 1));
            mx = fmaxf(mx, __shfl_xor_sync(0xffffffffu, mx, 2));
            float sum = 0.0f;
#pragma unroll
            for (int q2 = 0; q2 < 16; q2++) { vals[q2] = __expf(vals[q2] - mx); sum += vals[q2]; }
            sum += __shfl_xor_sync(0xffffffffu, sum, 1);
            sum += __shfl_xor_sync(0xffffffffu, sum, 2);
            float inv = 1.0f / sum;
#pragma unroll
            for (int nt = 0; nt < 8; nt++) {
                sc[mt][nt][rh * 2]     = vals[nt * 2]     * inv;
                sc[mt][nt][rh * 2 + 1] = vals[nt * 2 + 1] * inv;
            }
        }
    }

    unsigned pf[2][4][4];
#pragma unroll
    for (int mt = 0; mt < 2; mt++)
#pragma unroll
        for (int kc = 0; kc < 4; kc++) {
            pf[mt][kc][0] = pkbf(sc[mt][2 * kc][0],     sc[mt][2 * kc][1]);
            pf[mt][kc][1] = pkbf(sc[mt][2 * kc][2],     sc[mt][2 * kc][3]);
            pf[mt][kc][2] = pkbf(sc[mt][2 * kc + 1][0], sc[mt][2 * kc + 1][1]);
            pf[mt][kc][3] = pkbf(sc[mt][2 * kc + 1][2], sc[mt][2 * kc + 1][3]);
        }

    float oc[2][4][4];
#pragma unroll
    for (int mt = 0; mt < 2; mt++)
#pragma unroll
        for (int dt = 0; dt < 4; dt++)
#pragma unroll
            for (int c = 0; c < 4; c++) oc[mt][dt][c] = 0.0f;

#pragma unroll
    for (int kc = 0; kc < 4; kc++) {
        unsigned vfr[2][4];
#pragma unroll
        for (int dp = 0; dp < 2; dp++)
            ldsm4t(vfr[dp], s2u(&Vh[kc * 16 + (lane & 15)][dp * 16 + (lane >> 4) * 8]));
#pragma unroll
        for (int mt = 0; mt < 2; mt++)
#pragma unroll
            for (int dt = 0; dt < 4; dt++)
                mma_bf16(oc[mt][dt], pf[mt][kc], &vfr[dt >> 1][(dt & 1) * 2]);
    }

    const int head = hg * 4 + hh;
#pragma unroll
    for (int mt = 0; mt < 2; mt++) {
        const int i0 = (half * 2 + mt) * 16 + r;
#pragma unroll
        for (int rh = 0; rh < 2; rh++) {
            const int i = i0 + rh * 8;
            if (i < NTOK) {
                size_t rowb = ((size_t)win * NTOK + i) * 256 + head * 16;
#pragma unroll
                for (int dt = 0; dt < 4; dt++)
                    g_attnb[rowb + dt * 4 + cq] = pkbf(oc[mt][dt][rh * 2], oc[mt][dt][rh * 2 + 1]);
            }
        }
    }
}

// ---------------------------------------------------------------------------
// Kernel 3: proj GEMM. CTA 256x128, 512 threads, warp tile 64x32.
// ---------------------------------------------------------------------------
__global__ __launch_bounds__(512, 1) void proj_gemm(const float* __restrict__ x,
                                                    const float* __restrict__ bias,
                                                    float* __restrict__ out) {
    __shared__ __align__(16) unsigned short As[NSTAGE][256][STR];
    __shared__ __align__(16) unsigned short Bs[NSTAGE][128][STR];

    const int tid = threadIdx.x;
    const int row0 = blockIdx.y * 256, col0 = blockIdx.x * 128;
    const int lane = tid & 31, wid = tid >> 5;
    const int wm = wid >> 2, wn = wid & 3;

    float acc[16][4];
#pragma unroll
    for (int i = 0; i < 16; i++)
#pragma unroll
        for (int j = 0; j < 4; j++) acc[i][j] = 0.0f;

    const int a_sr = tid >> 1, a_ss = (tid & 1) * 2;
    const int b_sr = tid >> 2, b_ss = tid & 3;

    auto stage = [&](int buf, int kt) {
        const int k16 = kt * 16;
#pragma unroll
        for (int q = 0; q < 2; q++)
            cp16(s2u(&As[buf][a_sr][(a_ss + q) * 8]),
                 &g_attnb[(size_t)(row0 + a_sr) * 256 + k16 + (a_ss + q) * 4]);
        cp16(s2u(&Bs[buf][b_sr][b_ss * 8]),
             &g_wproj_t[(size_t)(col0 + b_sr) * 256 + k16 + b_ss * 4]);
    };

    stage(0, 0); cp_commit();
    stage(1, 1); cp_commit();

    const unsigned a_base = s2u(&As[0][0][0]);
    const unsigned b_base = s2u(&Bs[0][0][0]);
    const unsigned a_sz = 256 * STR * 2, b_sz = 128 * STR * 2;
    const int a_row = wm * 64 + (lane & 15);
    const int a_colB = (lane >> 4) * 16;
    const int b_row = wn * 32 + ((lane >> 4) & 1) * 8 + (lane & 7);
    const int b_colB = ((lane >> 3) & 1) * 16;

    int buf = 0, sbuf = 2;
#pragma unroll 1
    for (int t = 0; t < 16; t++) {
        if (t < 15) cp_wait1(); else cp_wait0();
        __syncthreads();
        if (t < 14) { stage(sbuf, t + 2); cp_commit(); }
        const unsigned ab = a_base + buf * a_sz;
        const unsigned bb = b_base + buf * b_sz;
#pragma unroll
        for (int ks = 0; ks < 2; ks++) {
            unsigned afr[4][4], bfr[2][4];
#pragma unroll
            for (int mt = 0; mt < 4; mt++)
                ldsm4(afr[mt], ab + (unsigned)((a_row + mt * 16) * (STR * 2) + ks * 32 + a_colB));
#pragma unroll
            for (int n2 = 0; n2 < 2; n2++)
                ldsm4(bfr[n2], bb + (unsigned)((b_row + n2 * 16) * (STR * 2) + ks * 32 + b_colB));
#pragma unroll
            for (int mt = 0; mt < 4; mt++)
#pragma unroll
                for (int nt = 0; nt < 4; nt++)
                    mma_bf16(acc[mt * 4 + nt], afr[mt], &bfr[nt >> 1][(nt & 1) * 2]);
        }
        buf = (buf == NSTAGE - 1) ? 0 : buf + 1;
        sbuf = (sbuf == NSTAGE - 1) ? 0 : sbuf + 1;
    }

#pragma unroll
    for (int mt = 0; mt < 4; mt++) {
#pragma unroll
        for (int half = 0; half < 2; half++) {
            int r = row0 + wm * 64 + mt * 16 + (lane >> 2) + half * 8;
            size_t pix = (size_t)row_to_pixel(r) * CDIM;
#pragma unroll
            for (int nt = 0; nt < 4; nt++) {
                int c = col0 + wn * 32 + nt * 8 + (lane & 3) * 2;
                float2 bv2 = *reinterpret_cast<const float2*>(bias + c);
                float2 xv  = *reinterpret_cast<const float2*>(x + pix + c);
                float2 ov;
                ov.x = xv.x + acc[mt * 4 + nt][half * 2]     + bv2.x;
                ov.y = xv.y + acc[mt * 4 + nt][half * 2 + 1] + bv2.y;
                *reinterpret_cast<float2*>(&out[pix + c]) = ov;
            }
        }
    }
}

extern "C" void kernel_launch(void* const* d_in, const int* in_sizes, int n_in,
                              void* d_out, int out_size) {
    const float* x      = (const float*)d_in[0];
    const float* qkv_w  = (const float*)d_in[1];
    const float* qkv_b  = (const float*)d_in[2];
    const float* proj_w = (const float*)d_in[3];
    const float* proj_b = (const float*)d_in[4];
    const float* table  = (const float*)d_in[5];
    float* out = (float*)d_out;

    cvt_x_kernel<<<(NPIX * 512 / 4) / 256, 256>>>(x);
    wtrans_kernel<<<1536, 256>>>(qkv_w, 1536, 0);
    wtrans_kernel<<<512, 256>>>(proj_w, 512, 1);

    qkv_gemm<<<dim3(12, 196), 512>>>(qkv_b);
    attn_kernel<<<dim3(NWIN, 4), 256>>>(table);
    proj_gemm<<<dim3(4, 196), 512>>>(x, proj_b, out);
}